// round 15
// baseline (speedup 1.0000x reference)
#include <cuda_runtime.h>
#include <cuda_bf16.h>
#include <math_constants.h>
#include <cstdint>

#define BB 8
#define NN 4096
#define KNBR 20
#define DIMG 1024

// ---------------------------------------------------------------------------
// Scratch (device globals; no allocations allowed)
// ---------------------------------------------------------------------------
__device__ float    d_cat  [BB * NN * 192];
__device__ int      d_idx  [BB * NN * KNBR];
__device__ unsigned d_gu   [BB * DIMG];
__device__ float    d_gdot [BB * 256];
__device__ float    d_h8   [BB * NN * 256];
__device__ float    d_h9   [BB * NN * 256];
__device__ float    d_h10  [BB * NN * 128];
__device__ float    d_U    [BB * NN * 64];
__device__ float    d_V    [BB * NN * 64];
__device__ float    d_xx   [BB * NN];

__device__ __forceinline__ float lrelu(float y) { return y > 0.f ? y : 0.2f * y; }

__device__ __forceinline__ unsigned encf(float v) {
    unsigned u = __float_as_uint(v);
    return (u & 0x80000000u) ? ~u : (u | 0x80000000u);
}
__device__ __forceinline__ float decf(unsigned u) {
    return __uint_as_float((u & 0x80000000u) ? (u & 0x7fffffffu) : ~u);
}

__device__ __forceinline__ void cp_async16(uint32_t saddr, const void* g) {
    asm volatile("cp.async.cg.shared.global [%0], [%1], 16;"
                 :: "r"(saddr), "l"(g));
}

// Fully-unrolled register-resident top-K insertion (strict value order).
__device__ __forceinline__ void topk_insert(
    float (&tv)[KNBR], int (&ti)[KNBR], float v, int ii)
{
#pragma unroll
    for (int t = KNBR - 1; t >= 0; t--) {
        if (t == 0 || v <= tv[t - 1]) { tv[t] = v; ti[t] = ii; break; }
        tv[t] = tv[t - 1]; ti[t] = ti[t - 1];
    }
}

// ---------------------------------------------------------------------------
// KNN, C=3 : thread per row, reads x (B,3,N) directly
// ---------------------------------------------------------------------------
__global__ __launch_bounds__(128) void knn3_kernel(
    const float* __restrict__ x, int* __restrict__ idxo)
{
    const int TT = 64;
    int b = blockIdx.y;
    int n = blockIdx.x * blockDim.x + threadIdx.x;
    const float* base = x + (size_t)b * 3 * NN;

    float f0 = base[n];
    float f1 = base[NN + n];
    float f2 = base[2 * NN + n];
    float my2 = f0 * f0 + f1 * f1 + f2 * f2;

    float topv[KNBR]; int topi[KNBR];
#pragma unroll
    for (int i = 0; i < KNBR; i++) { topv[i] = -CUDART_INF_F; topi[i] = 0; }
    float thr = -CUDART_INF_F;

    __shared__ float tile[TT * 3];
    __shared__ float txx[TT];

    for (int m0 = 0; m0 < NN; m0 += TT) {
        __syncthreads();
        for (int e = threadIdx.x; e < TT * 3; e += blockDim.x) {
            int c = e >> 6, j = e & 63;
            tile[j * 3 + c] = base[c * NN + m0 + j];
        }
        __syncthreads();
        if (threadIdx.x < TT) {
            float a = tile[threadIdx.x * 3 + 0];
            float bq = tile[threadIdx.x * 3 + 1];
            float cq = tile[threadIdx.x * 3 + 2];
            txx[threadIdx.x] = a * a + bq * bq + cq * cq;
        }
        __syncthreads();
#pragma unroll 4
        for (int j = 0; j < TT; j++) {
            float dot = f0 * tile[j * 3 + 0] + f1 * tile[j * 3 + 1] + f2 * tile[j * 3 + 2];
            float v = 2.0f * dot - my2 - txx[j];
            if (v > thr) {
                topk_insert(topv, topi, v, m0 + j);
                thr = topv[KNBR - 1];
            }
        }
    }
    int* op = idxo + ((size_t)b * NN + n) * KNBR;
#pragma unroll
    for (int i = 0; i < KNBR; i++) op[i] = topi[i];
}

// ---------------------------------------------------------------------------
// xx[i] = ||feat[i]||^2 replicating EXACTLY the knn64 packed-FFMA2 lane
// arithmetic, so self-distance is exactly 0.
// ---------------------------------------------------------------------------
__global__ void xx_kernel(const float* __restrict__ feat, int stride,
                          float* __restrict__ xxo)
{
    int i = blockIdx.x * 256 + threadIdx.x;
    const float* r = feat + (size_t)i * stride;
    float d[4];
#pragma unroll
    for (int blk = 0; blk < 4; blk++) {
        float lo = 0.f, hi = 0.f;
#pragma unroll
        for (int p = 0; p < 8; p++) {
            float e = r[blk * 16 + p * 2];
            float o = r[blk * 16 + p * 2 + 1];
            lo = fmaf(e, e, lo);
            hi = fmaf(o, o, hi);
        }
        d[blk] = lo + hi;
    }
    xxo[i] = (d[0] + d[1]) + (d[2] + d[3]);
}

// ---------------------------------------------------------------------------
// KNN, C=64 : thread-per-row, cp.async double-buffered 128-candidate tiles,
// packed fma.rn.f32x2 dot, register-resident top-20. ONE sync per tile
// (the bottom sync is redundant: the next iteration's top sync orders all
// compute of tile ct before issue(ct+2) overwrites buffer ct&1).
// Dynamic smem: 2*(128*64 + 128) floats = 66560 B.
// ---------------------------------------------------------------------------
__global__ __launch_bounds__(128) void knn64_kernel(
    const float* __restrict__ feat, int stride, const float* __restrict__ xxg,
    int* __restrict__ idxo)
{
    const int TT = 128;
    const int C = 64;
    extern __shared__ __align__(16) float sm[];
    float* tileb = sm;                    // [2][TT*C]
    float* cxxb  = sm + 2 * TT * C;       // [2][TT]

    int b = blockIdx.y;
    int n = blockIdx.x * blockDim.x + threadIdx.x;
    const float* base = feat + (size_t)b * NN * stride;
    const float* xb = xxg + (size_t)b * NN;

    // load query row and pack into 32 f32x2 registers (once per row)
    unsigned long long qp[32];
#pragma unroll
    for (int q = 0; q < 16; q++) {
        float4 v = *(const float4*)&base[(size_t)n * stride + q * 4];
        asm("mov.b64 %0, {%1,%2};" : "=l"(qp[2 * q])     : "f"(v.x), "f"(v.y));
        asm("mov.b64 %0, {%1,%2};" : "=l"(qp[2 * q + 1]) : "f"(v.z), "f"(v.w));
    }
    float my2 = xb[n];

    float topv[KNBR]; int topi[KNBR];
#pragma unroll
    for (int i = 0; i < KNBR; i++) { topv[i] = -CUDART_INF_F; topi[i] = 0; }
    float thr = -CUDART_INF_F;

    uint32_t sb0 = (uint32_t)__cvta_generic_to_shared(tileb);
    uint32_t sc0 = (uint32_t)__cvta_generic_to_shared(cxxb);
    int tid = threadIdx.x;

    auto issue = [&](int ct) {
        int bf = ct & 1;
        int m0 = ct * TT;
        uint32_t sb = sb0 + bf * (TT * C * 4);
#pragma unroll
        for (int m = 0; m < 16; m++) {
            int idx4 = tid + m * 128;
            int j = idx4 >> 4, q = idx4 & 15;
            cp_async16(sb + (uint32_t)(j * C + q * 4) * 4,
                       &base[(size_t)(m0 + j) * stride + q * 4]);
        }
        if (tid < 32)
            cp_async16(sc0 + (uint32_t)(bf * TT + tid * 4) * 4, &xb[m0 + tid * 4]);
        asm volatile("cp.async.commit_group;");
    };

    issue(0);

    for (int ct = 0; ct < NN / TT; ct++) {
        asm volatile("cp.async.wait_group 0;");
        __syncthreads();                     // loads visible; prev compute done
        if (ct < NN / TT - 1) issue(ct + 1); // overlap next load w/ compute

        uint32_t tbase = sb0 + (ct & 1) * (TT * C * 4);
        const float* cx = &cxxb[(ct & 1) * TT];
        int m0 = ct * TT;
#pragma unroll 2
        for (int j = 0; j < TT; j++) {
            uint32_t taddr = tbase + (uint32_t)(j * C) * 4;
            unsigned long long a0 = 0ull, a1 = 0ull, a2 = 0ull, a3 = 0ull;
#pragma unroll
            for (int m = 0; m < 4; m++) {
                unsigned long long c0, c1, c2, c3;
                asm("ld.shared.v2.b64 {%0,%1}, [%2];"
                    : "=l"(c0), "=l"(c1) : "r"(taddr + m * 64 + 0));
                asm("ld.shared.v2.b64 {%0,%1}, [%2];"
                    : "=l"(c2), "=l"(c3) : "r"(taddr + m * 64 + 16));
                unsigned long long c4, c5, c6, c7;
                asm("ld.shared.v2.b64 {%0,%1}, [%2];"
                    : "=l"(c4), "=l"(c5) : "r"(taddr + m * 64 + 32));
                asm("ld.shared.v2.b64 {%0,%1}, [%2];"
                    : "=l"(c6), "=l"(c7) : "r"(taddr + m * 64 + 48));
                unsigned long long* ap = (m == 0) ? &a0 : (m == 1) ? &a1 : (m == 2) ? &a2 : &a3;
                asm("fma.rn.f32x2 %0, %1, %2, %0;" : "+l"(*ap) : "l"(qp[m * 8 + 0]), "l"(c0));
                asm("fma.rn.f32x2 %0, %1, %2, %0;" : "+l"(*ap) : "l"(qp[m * 8 + 1]), "l"(c1));
                asm("fma.rn.f32x2 %0, %1, %2, %0;" : "+l"(*ap) : "l"(qp[m * 8 + 2]), "l"(c2));
                asm("fma.rn.f32x2 %0, %1, %2, %0;" : "+l"(*ap) : "l"(qp[m * 8 + 3]), "l"(c3));
                asm("fma.rn.f32x2 %0, %1, %2, %0;" : "+l"(*ap) : "l"(qp[m * 8 + 4]), "l"(c4));
                asm("fma.rn.f32x2 %0, %1, %2, %0;" : "+l"(*ap) : "l"(qp[m * 8 + 5]), "l"(c5));
                asm("fma.rn.f32x2 %0, %1, %2, %0;" : "+l"(*ap) : "l"(qp[m * 8 + 6]), "l"(c6));
                asm("fma.rn.f32x2 %0, %1, %2, %0;" : "+l"(*ap) : "l"(qp[m * 8 + 7]), "l"(c7));
            }
            float lA, hA, lB, hB, lC, hC, lD, hD;
            asm("mov.b64 {%0,%1}, %2;" : "=f"(lA), "=f"(hA) : "l"(a0));
            asm("mov.b64 {%0,%1}, %2;" : "=f"(lB), "=f"(hB) : "l"(a1));
            asm("mov.b64 {%0,%1}, %2;" : "=f"(lC), "=f"(hC) : "l"(a2));
            asm("mov.b64 {%0,%1}, %2;" : "=f"(lD), "=f"(hD) : "l"(a3));
            float dA = lA + hA, dB = lB + hB, dC = lC + hC, dD = lD + hD;
            float v = 2.0f * ((dA + dB) + (dC + dD)) - my2 - cx[j];
            if (v > thr) {
                topk_insert(topv, topi, v, m0 + j);
                thr = topv[KNBR - 1];
            }
        }
        // no bottom sync: next iteration's top sync provides the ordering
    }
    int* op = idxo + ((size_t)b * NN + n) * KNBR;
#pragma unroll
    for (int i = 0; i < KNBR; i++) op[i] = topi[i];
}

// ---------------------------------------------------------------------------
// Stage-1 U'/V' (CIN=3), reads x (B,3,N) directly
// ---------------------------------------------------------------------------
__global__ __launch_bounds__(256) void uv3_kernel(
    const float* __restrict__ x, const float* __restrict__ w,
    const float* __restrict__ sv, const float* __restrict__ bv,
    float* __restrict__ U, float* __restrict__ V)
{
    __shared__ float wa[64 * 3], wd[64 * 3], ss[64], bb[64];
    int tid = threadIdx.x;
    if (tid < 64) {
#pragma unroll
        for (int c = 0; c < 3; c++) {
            wa[tid * 3 + c] = w[tid * 6 + c];
            wd[tid * 3 + c] = w[tid * 6 + 3 + c] - w[tid * 6 + c];
        }
        ss[tid] = sv[tid]; bb[tid] = bv[tid];
    }
    __syncthreads();
    int warp = tid >> 5, lane = tid & 31;
    int i = blockIdx.x * 8 + warp;
    int b = i >> 12, n = i & (NN - 1);
    const float* bx = x + (size_t)b * 3 * NN;
    float x0 = bx[n], x1 = bx[NN + n], x2 = bx[2 * NN + n];
#pragma unroll
    for (int h = 0; h < 2; h++) {
        int o = lane + h * 32;
        float u = ss[o] * (wa[o * 3] * x0 + wa[o * 3 + 1] * x1 + wa[o * 3 + 2] * x2);
        float v = ss[o] * (wd[o * 3] * x0 + wd[o * 3 + 1] * x1 + wd[o * 3 + 2] * x2) + bb[o];
        U[(size_t)i * 64 + o] = u;
        V[(size_t)i * 64 + o] = v;
    }
}

// ---------------------------------------------------------------------------
// uv64: one-shot K=64 dual GEMM (wdiff folded)
// ---------------------------------------------------------------------------
__global__ __launch_bounds__(256) void uv64_kernel(
    const float* __restrict__ A, int lda,
    const float* __restrict__ w,
    const float* __restrict__ sv, const float* __restrict__ bv,
    float* __restrict__ U, float* __restrict__ V)
{
    extern __shared__ float sm[];
    float (*As)[68] = (float(*)[68])sm;
    float (*Wa)[68] = (float(*)[68])(sm + 64 * 68);
    float (*Wd)[68] = (float(*)[68])(sm + 2 * 64 * 68);

    int tid = threadIdx.x;
    int rowBase = blockIdx.x * 64;
    int r = tid >> 2, q0 = (tid & 3) * 4;

#pragma unroll
    for (int q = q0; q < q0 + 4; q++) {
        float4 a4 = *(const float4*)&A[(size_t)(rowBase + r) * lda + q * 4];
        As[q * 4 + 0][r] = a4.x; As[q * 4 + 1][r] = a4.y;
        As[q * 4 + 2][r] = a4.z; As[q * 4 + 3][r] = a4.w;
        float4 wa4 = *(const float4*)&w[r * 128 + q * 4];
        float4 wb4 = *(const float4*)&w[r * 128 + 64 + q * 4];
        Wa[q * 4 + 0][r] = wa4.x; Wa[q * 4 + 1][r] = wa4.y;
        Wa[q * 4 + 2][r] = wa4.z; Wa[q * 4 + 3][r] = wa4.w;
        Wd[q * 4 + 0][r] = wb4.x - wa4.x; Wd[q * 4 + 1][r] = wb4.y - wa4.y;
        Wd[q * 4 + 2][r] = wb4.z - wa4.z; Wd[q * 4 + 3][r] = wb4.w - wa4.w;
    }
    __syncthreads();

    int ty = tid >> 4, tx = tid & 15;
    float au[4][4] = {}, av[4][4] = {};
#pragma unroll 8
    for (int k = 0; k < 64; k++) {
        float4 a = *(const float4*)&As[k][ty * 4];
        float4 u = *(const float4*)&Wa[k][tx * 4];
        float4 d = *(const float4*)&Wd[k][tx * 4];
        au[0][0] += a.x * u.x; au[0][1] += a.x * u.y; au[0][2] += a.x * u.z; au[0][3] += a.x * u.w;
        au[1][0] += a.y * u.x; au[1][1] += a.y * u.y; au[1][2] += a.y * u.z; au[1][3] += a.y * u.w;
        au[2][0] += a.z * u.x; au[2][1] += a.z * u.y; au[2][2] += a.z * u.z; au[2][3] += a.z * u.w;
        au[3][0] += a.w * u.x; au[3][1] += a.w * u.y; au[3][2] += a.w * u.z; au[3][3] += a.w * u.w;
        av[0][0] += a.x * d.x; av[0][1] += a.x * d.y; av[0][2] += a.x * d.z; av[0][3] += a.x * d.w;
        av[1][0] += a.y * d.x; av[1][1] += a.y * d.y; av[1][2] += a.y * d.z; av[1][3] += a.y * d.w;
        av[2][0] += a.z * d.x; av[2][1] += a.z * d.y; av[2][2] += a.z * d.z; av[2][3] += a.z * d.w;
        av[3][0] += a.w * d.x; av[3][1] += a.w * d.y; av[3][2] += a.w * d.z; av[3][3] += a.w * d.w;
    }
#pragma unroll
    for (int j = 0; j < 4; j++) {
        int o = tx * 4 + j;
        float sc = sv[o], bi = bv[o];
#pragma unroll
        for (int i = 0; i < 4; i++) {
            size_t rr = rowBase + ty * 4 + i;
            U[rr * 64 + o] = au[i][j] * sc;
            V[rr * 64 + o] = av[i][j] * sc + bi;
        }
    }
}

// ---------------------------------------------------------------------------
// gemm2gf: layer-2 GEMM (FFMA2 inner loop) with fused gather-A and max-over-k.
// ---------------------------------------------------------------------------
__global__ __launch_bounds__(256) void gemm2gf_kernel(
    const float* __restrict__ U, const float* __restrict__ Vv,
    const int* __restrict__ idx, const float* __restrict__ W,
    const float* __restrict__ sv, const float* __restrict__ bv,
    float* __restrict__ cat, int off)
{
    __shared__ __align__(16) float As[64][68];
    __shared__ __align__(16) float Ws[64][68];
    int tid = threadIdx.x;
    int i0 = blockIdx.x * 3;
    int r = tid >> 2, q0 = (tid & 3) * 4;
    {
        int i = i0 + r / 20;
        if (i >= BB * NN) i = BB * NN - 1;
        int p = i * 20 + (r % 20);
        int j = idx[p];
        int rbase = (i >> 12) << 12;
        const float4* urow = (const float4*)&U[(size_t)(rbase + j) * 64];
        const float4* vrow = (const float4*)&Vv[(size_t)i * 64];
#pragma unroll
        for (int q = q0; q < q0 + 4; q++) {
            float4 u = urow[q], v = vrow[q];
            As[q * 4 + 0][r] = lrelu(u.x + v.x);
            As[q * 4 + 1][r] = lrelu(u.y + v.y);
            As[q * 4 + 2][r] = lrelu(u.z + v.z);
            As[q * 4 + 3][r] = lrelu(u.w + v.w);
            float4 w4 = *(const float4*)&W[r * 64 + q * 4];
            Ws[q * 4 + 0][r] = w4.x; Ws[q * 4 + 1][r] = w4.y;
            Ws[q * 4 + 2][r] = w4.z; Ws[q * 4 + 3][r] = w4.w;
        }
    }
    __syncthreads();
    int ty = tid >> 4, tx = tid & 15;
    uint32_t wsB = (uint32_t)__cvta_generic_to_shared(&Ws[0][0]);
    unsigned long long accp[4][2] = {};
#pragma unroll 16
    for (int k = 0; k < 64; k++) {
        float4 a = *(const float4*)&As[k][ty * 4];
        unsigned long long wlo, whi;
        asm("ld.shared.v2.b64 {%0,%1}, [%2];"
            : "=l"(wlo), "=l"(whi) : "r"(wsB + (uint32_t)((k * 68 + tx * 4) * 4)));
        unsigned long long ax, ay, az, aw;
        asm("mov.b64 %0, {%1,%1};" : "=l"(ax) : "f"(a.x));
        asm("mov.b64 %0, {%1,%1};" : "=l"(ay) : "f"(a.y));
        asm("mov.b64 %0, {%1,%1};" : "=l"(az) : "f"(a.z));
        asm("mov.b64 %0, {%1,%1};" : "=l"(aw) : "f"(a.w));
        asm("fma.rn.f32x2 %0, %1, %2, %0;" : "+l"(accp[0][0]) : "l"(ax), "l"(wlo));
        asm("fma.rn.f32x2 %0, %1, %2, %0;" : "+l"(accp[0][1]) : "l"(ax), "l"(whi));
        asm("fma.rn.f32x2 %0, %1, %2, %0;" : "+l"(accp[1][0]) : "l"(ay), "l"(wlo));
        asm("fma.rn.f32x2 %0, %1, %2, %0;" : "+l"(accp[1][1]) : "l"(ay), "l"(whi));
        asm("fma.rn.f32x2 %0, %1, %2, %0;" : "+l"(accp[2][0]) : "l"(az), "l"(wlo));
        asm("fma.rn.f32x2 %0, %1, %2, %0;" : "+l"(accp[2][1]) : "l"(az), "l"(whi));
        asm("fma.rn.f32x2 %0, %1, %2, %0;" : "+l"(accp[3][0]) : "l"(aw), "l"(wlo));
        asm("fma.rn.f32x2 %0, %1, %2, %0;" : "+l"(accp[3][1]) : "l"(aw), "l"(whi));
    }
    float acc[4][4];
#pragma unroll
    for (int i = 0; i < 4; i++) {
        asm("mov.b64 {%0,%1}, %2;" : "=f"(acc[i][0]), "=f"(acc[i][1]) : "l"(accp[i][0]));
        asm("mov.b64 {%0,%1}, %2;" : "=f"(acc[i][2]), "=f"(acc[i][3]) : "l"(accp[i][1]));
    }

    float sc0 = sv[tx * 4 + 0], sc1 = sv[tx * 4 + 1], sc2 = sv[tx * 4 + 2], sc3 = sv[tx * 4 + 3];
    float bi0 = bv[tx * 4 + 0], bi1 = bv[tx * 4 + 1], bi2 = bv[tx * 4 + 2], bi3 = bv[tx * 4 + 3];
    __syncthreads();
#pragma unroll
    for (int i2 = 0; i2 < 4; i2++) {
        float4 vv;
        vv.x = lrelu(acc[i2][0] * sc0 + bi0);
        vv.y = lrelu(acc[i2][1] * sc1 + bi1);
        vv.z = lrelu(acc[i2][2] * sc2 + bi2);
        vv.w = lrelu(acc[i2][3] * sc3 + bi3);
        *(float4*)&As[ty * 4 + i2][tx * 4] = vv;
    }
    __syncthreads();
    if (tid < 192) {
        int pp = tid >> 6, o = tid & 63;
        int i = i0 + pp;
        if (i < BB * NN) {
            float m = As[pp * 20][o];
#pragma unroll
            for (int kk = 1; kk < KNBR; kk++)
                m = fmaxf(m, As[pp * 20 + kk][o]);
            cat[(size_t)i * 192 + off + o] = m;
        }
    }
}

// ---------------------------------------------------------------------------
// Stage-3 fused: out = max_k lrelu(U'[idx] + V'[i])
// ---------------------------------------------------------------------------
__global__ __launch_bounds__(256) void stage3_kernel(
    const float* __restrict__ U, const float* __restrict__ Vv,
    const int* __restrict__ idx, float* __restrict__ out)
{
    int tid = threadIdx.x, warp = tid >> 5, lane = tid & 31;
    int i = blockIdx.x * 8 + warp;
    int rbase = (i >> 12) << 12;
    float v0 = Vv[(size_t)i * 64 + lane];
    float v1 = Vv[(size_t)i * 64 + lane + 32];
    float m0 = -CUDART_INF_F, m1 = -CUDART_INF_F;
#pragma unroll
    for (int k = 0; k < KNBR; k++) {
        int j = idx[i * KNBR + k];
        const float* ur = &U[(size_t)(rbase + j) * 64];
        m0 = fmaxf(m0, lrelu(ur[lane] + v0));
        m1 = fmaxf(m1, lrelu(ur[lane + 32] + v1));
    }
    out[(size_t)i * 192 + 128 + lane] = m0;
    out[(size_t)i * 192 + 128 + lane + 32] = m1;
}

// ---------------------------------------------------------------------------
// Tiled fp32 GEMM (FFMA2 inner loop): 64x64x16 tiles, 4x4/thread.
// ---------------------------------------------------------------------------
template <int MODE, bool SB, bool EXT, bool LEAKY>
__global__ __launch_bounds__(256) void gemm_kernel(
    const float* __restrict__ A, int lda,
    const float* __restrict__ W, int ldw, int woff,
    const float* __restrict__ sv, const float* __restrict__ bv,
    const float* __restrict__ ext,
    float* __restrict__ outp, unsigned* __restrict__ gout,
    int Nout, int Ktot)
{
    __shared__ __align__(16) float As[16][68];
    __shared__ __align__(16) float Ws[16][68];
    __shared__ float cm[16][65];

    int tid = threadIdx.x;
    int tx = tid & 15, ty = tid >> 4;
    int rowBase = blockIdx.y * 64, colBase = blockIdx.x * 64;
    int lr = tid >> 2, lk = tid & 3;
    uint32_t wsB = (uint32_t)__cvta_generic_to_shared(&Ws[0][0]);

    unsigned long long accp[4][2] = {};

    for (int k0 = 0; k0 < Ktot; k0 += 16) {
        float4 av = *(const float4*)&A[(size_t)(rowBase + lr) * lda + k0 + lk * 4];
        float4 wv = make_float4(0.f, 0.f, 0.f, 0.f);
        if (colBase + lr < Nout)
            wv = *(const float4*)&W[(size_t)(colBase + lr) * ldw + woff + k0 + lk * 4];
        __syncthreads();
        As[lk * 4 + 0][lr] = av.x; As[lk * 4 + 1][lr] = av.y;
        As[lk * 4 + 2][lr] = av.z; As[lk * 4 + 3][lr] = av.w;
        Ws[lk * 4 + 0][lr] = wv.x; Ws[lk * 4 + 1][lr] = wv.y;
        Ws[lk * 4 + 2][lr] = wv.z; Ws[lk * 4 + 3][lr] = wv.w;
        __syncthreads();
#pragma unroll
        for (int k = 0; k < 16; k++) {
            float4 a = *(const float4*)&As[k][ty * 4];
            unsigned long long wlo, whi;
            asm("ld.shared.v2.b64 {%0,%1}, [%2];"
                : "=l"(wlo), "=l"(whi) : "r"(wsB + (uint32_t)((k * 68 + tx * 4) * 4)));
            unsigned long long ax, ay, az, aw;
            asm("mov.b64 %0, {%1,%1};" : "=l"(ax) : "f"(a.x));
            asm("mov.b64 %0, {%1,%1};" : "=l"(ay) : "f"(a.y));
            asm("mov.b64 %0, {%1,%1};" : "=l"(az) : "f"(a.z));
            asm("mov.b64 %0, {%1,%1};" : "=l"(aw) : "f"(a.w));
            asm("fma.rn.f32x2 %0, %1, %2, %0;" : "+l"(accp[0][0]) : "l"(ax), "l"(wlo));
            asm("fma.rn.f32x2 %0, %1, %2, %0;" : "+l"(accp[0][1]) : "l"(ax), "l"(whi));
            asm("fma.rn.f32x2 %0, %1, %2, %0;" : "+l"(accp[1][0]) : "l"(ay), "l"(wlo));
            asm("fma.rn.f32x2 %0, %1, %2, %0;" : "+l"(accp[1][1]) : "l"(ay), "l"(whi));
            asm("fma.rn.f32x2 %0, %1, %2, %0;" : "+l"(accp[2][0]) : "l"(az), "l"(wlo));
            asm("fma.rn.f32x2 %0, %1, %2, %0;" : "+l"(accp[2][1]) : "l"(az), "l"(whi));
            asm("fma.rn.f32x2 %0, %1, %2, %0;" : "+l"(accp[3][0]) : "l"(aw), "l"(wlo));
            asm("fma.rn.f32x2 %0, %1, %2, %0;" : "+l"(accp[3][1]) : "l"(aw), "l"(whi));
        }
    }

    float acc[4][4];
#pragma unroll
    for (int i = 0; i < 4; i++) {
        asm("mov.b64 {%0,%1}, %2;" : "=f"(acc[i][0]), "=f"(acc[i][1]) : "l"(accp[i][0]));
        asm("mov.b64 {%0,%1}, %2;" : "=f"(acc[i][2]), "=f"(acc[i][3]) : "l"(accp[i][1]));
    }

    int bidx = rowBase >> 12;

    if (MODE == 2) {
#pragma unroll
        for (int j = 0; j < 4; j++) {
            int o = colBase + tx * 4 + j;
            float sc = SB ? sv[o] : 1.f;
            float bi = SB ? bv[o] : 0.f;
            float m = -CUDART_INF_F;
#pragma unroll
            for (int i = 0; i < 4; i++) {
                float v = acc[i][j];
                if (SB) v = v * sc + bi;
                if (LEAKY) v = lrelu(v);
                m = fmaxf(m, v);
            }
            cm[ty][tx * 4 + j] = m;
        }
        __syncthreads();
        if (tid < 64) {
            float mm = cm[0][tid];
#pragma unroll
            for (int t = 1; t < 16; t++) mm = fmaxf(mm, cm[t][tid]);
            atomicMax(&gout[bidx * DIMG + colBase + tid], encf(mm));
        }
    } else if (MODE == 0) {
        float sc[4], bi[4], ex[4];
#pragma unroll
        for (int j = 0; j < 4; j++) {
            int o = colBase + tx * 4 + j;
            sc[j] = SB ? sv[o] : 1.f;
            bi[j] = SB ? bv[o] : 0.f;
            ex[j] = EXT ? ext[bidx * Nout + o] : 0.f;
        }
#pragma unroll
        for (int i = 0; i < 4; i++) {
            int r = rowBase + ty * 4 + i;
            float4 vv;
            float v0 = acc[i][0], v1 = acc[i][1], v2 = acc[i][2], v3 = acc[i][3];
            if (EXT) { v0 += ex[0]; v1 += ex[1]; v2 += ex[2]; v3 += ex[3]; }
            if (SB)  { v0 = v0 * sc[0] + bi[0]; v1 = v1 * sc[1] + bi[1];
                       v2 = v2 * sc[2] + bi[2]; v3 = v3 * sc[3] + bi[3]; }
            if (LEAKY) { v0 = lrelu(v0); v1 = lrelu(v1); v2 = lrelu(v2); v3 = lrelu(v3); }
            vv.x = v0; vv.y = v1; vv.z = v2; vv.w = v3;
            *(float4*)&outp[(size_t)r * Nout + colBase + tx * 4] = vv;
        }
    } else {
#pragma unroll
        for (int j = 0; j < 4; j++) {
            int o = colBase + tx * 4 + j;
#pragma unroll
            for (int i = 0; i < 4; i++) {
                int r = rowBase + ty * 4 + i;
                if (o < 13)
                    outp[((size_t)bidx * 13 + o) * NN + (r & (NN - 1))] = acc[i][j];
            }
        }
    }
}

// ---------------------------------------------------------------------------
// g-buffer init + gdot = w8[:, :1024] @ g  (per batch)
// ---------------------------------------------------------------------------
__global__ void zero_gu_kernel(unsigned* __restrict__ gu) {
    int t = blockIdx.x * blockDim.x + threadIdx.x;
    if (t < BB * DIMG) gu[t] = 0u;
}

__global__ __launch_bounds__(256) void gdot_kernel(
    const unsigned* __restrict__ gu, const float* __restrict__ w8, float* __restrict__ gdot)
{
    int b = blockIdx.x;
    __shared__ float gsh[DIMG];
    for (int i = threadIdx.x; i < DIMG; i += blockDim.x) gsh[i] = decf(gu[b * DIMG + i]);
    __syncthreads();
    int warp = threadIdx.x >> 5, lane = threadIdx.x & 31;
    for (int o = warp * 32; o < warp * 32 + 32; o++) {
        float accv = 0.f;
        for (int c = lane; c < DIMG; c += 32)
            accv += w8[(size_t)o * 1216 + c] * gsh[c];
#pragma unroll
        for (int off = 16; off; off >>= 1)
            accv += __shfl_down_sync(0xffffffffu, accv, off);
        if (lane == 0) gdot[b * 256 + o] = accv;
    }
}

// ---------------------------------------------------------------------------
// Launcher
// ---------------------------------------------------------------------------
extern "C" void kernel_launch(void* const* d_in, const int* in_sizes, int n_in,
                              void* d_out, int out_size)
{
    (void)in_sizes; (void)n_in; (void)out_size;

    const float* x   = (const float*)d_in[0];
    const float* w1  = (const float*)d_in[1];
    const float* s1  = (const float*)d_in[2];
    const float* b1  = (const float*)d_in[3];
    const float* w2  = (const float*)d_in[4];
    const float* s2  = (const float*)d_in[5];
    const float* b2  = (const float*)d_in[6];
    const float* w3  = (const float*)d_in[7];
    const float* s3  = (const float*)d_in[8];
    const float* b3  = (const float*)d_in[9];
    const float* w4  = (const float*)d_in[10];
    const float* s4  = (const float*)d_in[11];
    const float* b4  = (const float*)d_in[12];
    const float* w5  = (const float*)d_in[13];
    const float* s5  = (const float*)d_in[14];
    const float* b5  = (const float*)d_in[15];
    const float* w6  = (const float*)d_in[16];
    const float* s6  = (const float*)d_in[17];
    const float* b6  = (const float*)d_in[18];
    const float* w8  = (const float*)d_in[19];
    const float* s8  = (const float*)d_in[20];
    const float* b8  = (const float*)d_in[21];
    const float* w9  = (const float*)d_in[22];
    const float* s9  = (const float*)d_in[23];
    const float* b9  = (const float*)d_in[24];
    const float* w10 = (const float*)d_in[25];
    const float* s10 = (const float*)d_in[26];
    const float* b10 = (const float*)d_in[27];
    const float* w11 = (const float*)d_in[28];
    float* out = (float*)d_out;

    void* p;
    cudaGetSymbolAddress(&p, d_cat);   float*    cat   = (float*)p;
    cudaGetSymbolAddress(&p, d_idx);   int*      idx   = (int*)p;
    cudaGetSymbolAddress(&p, d_gu);    unsigned* gu    = (unsigned*)p;
    cudaGetSymbolAddress(&p, d_gdot);  float*    gdot  = (float*)p;
    cudaGetSymbolAddress(&p, d_h8);    float*    h8    = (float*)p;
    cudaGetSymbolAddress(&p, d_h9);    float*    h9    = (float*)p;
    cudaGetSymbolAddress(&p, d_h10);   float*    h10   = (float*)p;
    cudaGetSymbolAddress(&p, d_U);     float*    U     = (float*)p;
    cudaGetSymbolAddress(&p, d_V);     float*    V     = (float*)p;
    cudaGetSymbolAddress(&p, d_xx);    float*    xxb   = (float*)p;

    const int uvSmem  = 3 * 64 * 68 * 4;           // 52224
    const int knnSmem = (2 * 128 * 64 + 2 * 128) * 4;  // 66560
    cudaFuncSetAttribute((const void*)uv64_kernel,
                         cudaFuncAttributeMaxDynamicSharedMemorySize, uvSmem);
    cudaFuncSetAttribute((const void*)knn64_kernel,
                         cudaFuncAttributeMaxDynamicSharedMemorySize, knnSmem);

    const int PTS = BB * NN;                 // 32768
    const int G2F = (PTS + 2) / 3;
    dim3 knnGrid(NN / 128, BB);

    // stage 1 (3 -> 64 -> 64)
    knn3_kernel<<<knnGrid, 128>>>(x, idx);
    uv3_kernel<<<PTS / 8, 256>>>(x, w1, s1, b1, U, V);
    gemm2gf_kernel<<<G2F, 256>>>(U, V, idx, w2, s2, b2, cat, 0);

    // stage 2 (64 -> 64 -> 64)
    xx_kernel<<<PTS / 256, 256>>>(cat + 0, 192, xxb);
    knn64_kernel<<<knnGrid, 128, knnSmem>>>(cat + 0, 192, xxb, idx);
    uv64_kernel<<<PTS / 64, 256, uvSmem>>>(cat + 0, 192, w3, s3, b3, U, V);
    gemm2gf_kernel<<<G2F, 256>>>(U, V, idx, w4, s4, b4, cat, 64);

    // stage 3 (64 -> 64, single layer, fully fused)
    xx_kernel<<<PTS / 256, 256>>>(cat + 64, 192, xxb);
    knn64_kernel<<<knnGrid, 128, knnSmem>>>(cat + 64, 192, xxb, idx);
    uv64_kernel<<<PTS / 64, 256, uvSmem>>>(cat + 64, 192, w5, s5, b5, U, V);
    stage3_kernel<<<PTS / 8, 256>>>(U, V, idx, cat);

    // cbl6 (192 -> 1024) fused with max-over-N (smem-reduced atomics)
    zero_gu_kernel<<<(BB * DIMG + 255) / 256, 256>>>(gu);
    gemm_kernel<2, true, false, true><<<dim3(DIMG / 64, PTS / 64), 256>>>(
        cat, 192, w6, 192, 0, s6, b6, nullptr, nullptr, gu, DIMG, 192);

    // gdot[b,o] = w8[o, :1024] . g[b]
    gdot_kernel<<<BB, 256>>>(gu, w8, gdot);

    // cbl8: (gdot + w8[:,1024:] @ cat) * s8 + b8, leaky
    gemm_kernel<0, true, true, true><<<dim3(256 / 64, PTS / 64), 256>>>(
        cat, 192, w8, 1216, 1024, s8, b8, gdot, h8, nullptr, 256, 192);

    // cbl9
    gemm_kernel<0, true, false, true><<<dim3(256 / 64, PTS / 64), 256>>>(
        h8, 256, w9, 256, 0, s9, b9, nullptr, h9, nullptr, 256, 256);

    // cbl10
    gemm_kernel<0, true, false, true><<<dim3(128 / 64, PTS / 64), 256>>>(
        h9, 256, w10, 256, 0, s10, b10, nullptr, h10, nullptr, 128, 256);

    // classifier + transpose to (B,13,N)
    gemm_kernel<1, false, false, false><<<dim3(1, PTS / 64), 256>>>(
        h10, 128, w11, 128, 0, nullptr, nullptr, nullptr, out, nullptr, 13, 128);
}

// round 16
// speedup vs baseline: 2.0848x; 2.0848x over previous
#include <cuda_runtime.h>
#include <cuda_bf16.h>
#include <math_constants.h>
#include <cstdint>

#define BB 8
#define NN 4096
#define KNBR 20
#define DIMG 1024

// ---------------------------------------------------------------------------
// Scratch (device globals; no allocations allowed)
// ---------------------------------------------------------------------------
__device__ float    d_cat  [BB * NN * 192];
__device__ int      d_idx  [BB * NN * KNBR];
__device__ unsigned d_gu   [BB * DIMG];
__device__ float    d_gdot [BB * 256];
__device__ float    d_h8   [BB * NN * 256];
__device__ float    d_h9   [BB * NN * 256];
__device__ float    d_h10  [BB * NN * 128];
__device__ float    d_U    [BB * NN * 64];
__device__ float    d_V    [BB * NN * 64];
__device__ float    d_xx   [BB * NN];

__device__ __forceinline__ float lrelu(float y) { return y > 0.f ? y : 0.2f * y; }

__device__ __forceinline__ unsigned encf(float v) {
    unsigned u = __float_as_uint(v);
    return (u & 0x80000000u) ? ~u : (u | 0x80000000u);
}
__device__ __forceinline__ float decf(unsigned u) {
    return __uint_as_float((u & 0x80000000u) ? (u & 0x7fffffffu) : ~u);
}

__device__ __forceinline__ void cp_async16(uint32_t saddr, const void* g) {
    asm volatile("cp.async.cg.shared.global [%0], [%1], 16;"
                 :: "r"(saddr), "l"(g));
}

// Fully-unrolled register-resident top-K insertion (strict value order).
__device__ __forceinline__ void topk_insert(
    float (&tv)[KNBR], int (&ti)[KNBR], float v, int ii)
{
#pragma unroll
    for (int t = KNBR - 1; t >= 0; t--) {
        if (t == 0 || v <= tv[t - 1]) { tv[t] = v; ti[t] = ii; break; }
        tv[t] = tv[t - 1]; ti[t] = ti[t - 1];
    }
}

// ---------------------------------------------------------------------------
// KNN, C=3 : thread per row, reads x (B,3,N) directly
// ---------------------------------------------------------------------------
__global__ __launch_bounds__(128) void knn3_kernel(
    const float* __restrict__ x, int* __restrict__ idxo)
{
    const int TT = 64;
    int b = blockIdx.y;
    int n = blockIdx.x * blockDim.x + threadIdx.x;
    const float* base = x + (size_t)b * 3 * NN;

    float f0 = base[n];
    float f1 = base[NN + n];
    float f2 = base[2 * NN + n];
    float my2 = f0 * f0 + f1 * f1 + f2 * f2;

    float topv[KNBR]; int topi[KNBR];
#pragma unroll
    for (int i = 0; i < KNBR; i++) { topv[i] = -CUDART_INF_F; topi[i] = 0; }
    float thr = -CUDART_INF_F;

    __shared__ float tile[TT * 3];
    __shared__ float txx[TT];

    for (int m0 = 0; m0 < NN; m0 += TT) {
        __syncthreads();
        for (int e = threadIdx.x; e < TT * 3; e += blockDim.x) {
            int c = e >> 6, j = e & 63;
            tile[j * 3 + c] = base[c * NN + m0 + j];
        }
        __syncthreads();
        if (threadIdx.x < TT) {
            float a = tile[threadIdx.x * 3 + 0];
            float bq = tile[threadIdx.x * 3 + 1];
            float cq = tile[threadIdx.x * 3 + 2];
            txx[threadIdx.x] = a * a + bq * bq + cq * cq;
        }
        __syncthreads();
#pragma unroll 4
        for (int j = 0; j < TT; j++) {
            float dot = f0 * tile[j * 3 + 0] + f1 * tile[j * 3 + 1] + f2 * tile[j * 3 + 2];
            float v = 2.0f * dot - my2 - txx[j];
            if (v > thr) {
                topk_insert(topv, topi, v, m0 + j);
                thr = topv[KNBR - 1];
            }
        }
    }
    int* op = idxo + ((size_t)b * NN + n) * KNBR;
#pragma unroll
    for (int i = 0; i < KNBR; i++) op[i] = topi[i];
}

// ---------------------------------------------------------------------------
// xx[i] = ||feat[i]||^2 replicating EXACTLY the knn64 packed-FFMA2 lane
// arithmetic, so self-distance is exactly 0.
// ---------------------------------------------------------------------------
__global__ void xx_kernel(const float* __restrict__ feat, int stride,
                          float* __restrict__ xxo)
{
    int i = blockIdx.x * 256 + threadIdx.x;
    const float* r = feat + (size_t)i * stride;
    float d[4];
#pragma unroll
    for (int blk = 0; blk < 4; blk++) {
        float lo = 0.f, hi = 0.f;
#pragma unroll
        for (int p = 0; p < 8; p++) {
            float e = r[blk * 16 + p * 2];
            float o = r[blk * 16 + p * 2 + 1];
            lo = fmaf(e, e, lo);
            hi = fmaf(o, o, hi);
        }
        d[blk] = lo + hi;
    }
    xxo[i] = (d[0] + d[1]) + (d[2] + d[3]);
}

// ---------------------------------------------------------------------------
// KNN, C=64 : thread-per-row, cp.async double-buffered 64-candidate tiles,
// packed fma.rn.f32x2 dot (32 FFMA2/candidate), register-resident top-20.
// ONE sync per tile: the bottom sync is redundant because the next
// iteration's top sync (after wait_group) orders all compute of tile ct
// before issue(ct+2) can overwrite buffer ct&1.
// ---------------------------------------------------------------------------
__global__ __launch_bounds__(128) void knn64_kernel(
    const float* __restrict__ feat, int stride, const float* __restrict__ xxg,
    int* __restrict__ idxo)
{
    const int TT = 64;
    const int C = 64;
    int b = blockIdx.y;
    int n = blockIdx.x * blockDim.x + threadIdx.x;
    const float* base = feat + (size_t)b * NN * stride;
    const float* xb = xxg + (size_t)b * NN;

    // load query row and pack into 32 f32x2 registers (once per row)
    unsigned long long qp[32];
#pragma unroll
    for (int q = 0; q < 16; q++) {
        float4 v = *(const float4*)&base[(size_t)n * stride + q * 4];
        asm("mov.b64 %0, {%1,%2};" : "=l"(qp[2 * q])     : "f"(v.x), "f"(v.y));
        asm("mov.b64 %0, {%1,%2};" : "=l"(qp[2 * q + 1]) : "f"(v.z), "f"(v.w));
    }
    float my2 = xb[n];

    float topv[KNBR]; int topi[KNBR];
#pragma unroll
    for (int i = 0; i < KNBR; i++) { topv[i] = -CUDART_INF_F; topi[i] = 0; }
    float thr = -CUDART_INF_F;

    __shared__ __align__(16) float tile[2][TT * C];
    __shared__ __align__(16) float cxx[2][TT];

    uint32_t sb0 = (uint32_t)__cvta_generic_to_shared(&tile[0][0]);
    uint32_t sc0 = (uint32_t)__cvta_generic_to_shared(&cxx[0][0]);
    int tid = threadIdx.x;

    auto issue = [&](int ct) {
        int bf = ct & 1;
        int m0 = ct * TT;
        uint32_t sb = sb0 + bf * (TT * C * 4);
#pragma unroll
        for (int m = 0; m < 8; m++) {
            int idx4 = tid + m * 128;
            int j = idx4 >> 4, q = idx4 & 15;
            cp_async16(sb + (uint32_t)(j * C + q * 4) * 4,
                       &base[(size_t)(m0 + j) * stride + q * 4]);
        }
        if (tid < 16)
            cp_async16(sc0 + (uint32_t)(bf * TT + tid * 4) * 4, &xb[m0 + tid * 4]);
        asm volatile("cp.async.commit_group;");
    };

    issue(0);

    for (int ct = 0; ct < NN / TT; ct++) {
        asm volatile("cp.async.wait_group 0;");
        __syncthreads();                     // loads visible; prev compute done
        if (ct < NN / TT - 1) issue(ct + 1); // overlap next load w/ compute

        uint32_t tbase = sb0 + (ct & 1) * (TT * C * 4);
        const float* cx = cxx[ct & 1];
        int m0 = ct * TT;
#pragma unroll 2
        for (int j = 0; j < TT; j++) {
            uint32_t taddr = tbase + (uint32_t)(j * C) * 4;
            unsigned long long a0 = 0ull, a1 = 0ull, a2 = 0ull, a3 = 0ull;
#pragma unroll
            for (int m = 0; m < 4; m++) {
                unsigned long long c0, c1, c2, c3;
                asm("ld.shared.v2.b64 {%0,%1}, [%2];"
                    : "=l"(c0), "=l"(c1) : "r"(taddr + m * 64 + 0));
                asm("ld.shared.v2.b64 {%0,%1}, [%2];"
                    : "=l"(c2), "=l"(c3) : "r"(taddr + m * 64 + 16));
                unsigned long long c4, c5, c6, c7;
                asm("ld.shared.v2.b64 {%0,%1}, [%2];"
                    : "=l"(c4), "=l"(c5) : "r"(taddr + m * 64 + 32));
                asm("ld.shared.v2.b64 {%0,%1}, [%2];"
                    : "=l"(c6), "=l"(c7) : "r"(taddr + m * 64 + 48));
                unsigned long long* ap = (m == 0) ? &a0 : (m == 1) ? &a1 : (m == 2) ? &a2 : &a3;
                asm("fma.rn.f32x2 %0, %1, %2, %0;" : "+l"(*ap) : "l"(qp[m * 8 + 0]), "l"(c0));
                asm("fma.rn.f32x2 %0, %1, %2, %0;" : "+l"(*ap) : "l"(qp[m * 8 + 1]), "l"(c1));
                asm("fma.rn.f32x2 %0, %1, %2, %0;" : "+l"(*ap) : "l"(qp[m * 8 + 2]), "l"(c2));
                asm("fma.rn.f32x2 %0, %1, %2, %0;" : "+l"(*ap) : "l"(qp[m * 8 + 3]), "l"(c3));
                asm("fma.rn.f32x2 %0, %1, %2, %0;" : "+l"(*ap) : "l"(qp[m * 8 + 4]), "l"(c4));
                asm("fma.rn.f32x2 %0, %1, %2, %0;" : "+l"(*ap) : "l"(qp[m * 8 + 5]), "l"(c5));
                asm("fma.rn.f32x2 %0, %1, %2, %0;" : "+l"(*ap) : "l"(qp[m * 8 + 6]), "l"(c6));
                asm("fma.rn.f32x2 %0, %1, %2, %0;" : "+l"(*ap) : "l"(qp[m * 8 + 7]), "l"(c7));
            }
            float lA, hA, lB, hB, lC, hC, lD, hD;
            asm("mov.b64 {%0,%1}, %2;" : "=f"(lA), "=f"(hA) : "l"(a0));
            asm("mov.b64 {%0,%1}, %2;" : "=f"(lB), "=f"(hB) : "l"(a1));
            asm("mov.b64 {%0,%1}, %2;" : "=f"(lC), "=f"(hC) : "l"(a2));
            asm("mov.b64 {%0,%1}, %2;" : "=f"(lD), "=f"(hD) : "l"(a3));
            float dA = lA + hA, dB = lB + hB, dC = lC + hC, dD = lD + hD;
            float v = 2.0f * ((dA + dB) + (dC + dD)) - my2 - cx[j];
            if (v > thr) {
                topk_insert(topv, topi, v, m0 + j);
                thr = topv[KNBR - 1];
            }
        }
        // no bottom sync: next iteration's top sync provides the ordering
    }
    int* op = idxo + ((size_t)b * NN + n) * KNBR;
#pragma unroll
    for (int i = 0; i < KNBR; i++) op[i] = topi[i];
}

// ---------------------------------------------------------------------------
// Stage-1 U'/V' (CIN=3), reads x (B,3,N) directly
// ---------------------------------------------------------------------------
__global__ __launch_bounds__(256) void uv3_kernel(
    const float* __restrict__ x, const float* __restrict__ w,
    const float* __restrict__ sv, const float* __restrict__ bv,
    float* __restrict__ U, float* __restrict__ V)
{
    __shared__ float wa[64 * 3], wd[64 * 3], ss[64], bb[64];
    int tid = threadIdx.x;
    if (tid < 64) {
#pragma unroll
        for (int c = 0; c < 3; c++) {
            wa[tid * 3 + c] = w[tid * 6 + c];
            wd[tid * 3 + c] = w[tid * 6 + 3 + c] - w[tid * 6 + c];
        }
        ss[tid] = sv[tid]; bb[tid] = bv[tid];
    }
    __syncthreads();
    int warp = tid >> 5, lane = tid & 31;
    int i = blockIdx.x * 8 + warp;
    int b = i >> 12, n = i & (NN - 1);
    const float* bx = x + (size_t)b * 3 * NN;
    float x0 = bx[n], x1 = bx[NN + n], x2 = bx[2 * NN + n];
#pragma unroll
    for (int h = 0; h < 2; h++) {
        int o = lane + h * 32;
        float u = ss[o] * (wa[o * 3] * x0 + wa[o * 3 + 1] * x1 + wa[o * 3 + 2] * x2);
        float v = ss[o] * (wd[o * 3] * x0 + wd[o * 3 + 1] * x1 + wd[o * 3 + 2] * x2) + bb[o];
        U[(size_t)i * 64 + o] = u;
        V[(size_t)i * 64 + o] = v;
    }
}

// ---------------------------------------------------------------------------
// uv64: one-shot K=64 dual GEMM (wdiff folded)
// ---------------------------------------------------------------------------
__global__ __launch_bounds__(256) void uv64_kernel(
    const float* __restrict__ A, int lda,
    const float* __restrict__ w,
    const float* __restrict__ sv, const float* __restrict__ bv,
    float* __restrict__ U, float* __restrict__ V)
{
    extern __shared__ float sm[];
    float (*As)[68] = (float(*)[68])sm;
    float (*Wa)[68] = (float(*)[68])(sm + 64 * 68);
    float (*Wd)[68] = (float(*)[68])(sm + 2 * 64 * 68);

    int tid = threadIdx.x;
    int rowBase = blockIdx.x * 64;
    int r = tid >> 2, q0 = (tid & 3) * 4;

#pragma unroll
    for (int q = q0; q < q0 + 4; q++) {
        float4 a4 = *(const float4*)&A[(size_t)(rowBase + r) * lda + q * 4];
        As[q * 4 + 0][r] = a4.x; As[q * 4 + 1][r] = a4.y;
        As[q * 4 + 2][r] = a4.z; As[q * 4 + 3][r] = a4.w;
        float4 wa4 = *(const float4*)&w[r * 128 + q * 4];
        float4 wb4 = *(const float4*)&w[r * 128 + 64 + q * 4];
        Wa[q * 4 + 0][r] = wa4.x; Wa[q * 4 + 1][r] = wa4.y;
        Wa[q * 4 + 2][r] = wa4.z; Wa[q * 4 + 3][r] = wa4.w;
        Wd[q * 4 + 0][r] = wb4.x - wa4.x; Wd[q * 4 + 1][r] = wb4.y - wa4.y;
        Wd[q * 4 + 2][r] = wb4.z - wa4.z; Wd[q * 4 + 3][r] = wb4.w - wa4.w;
    }
    __syncthreads();

    int ty = tid >> 4, tx = tid & 15;
    float au[4][4] = {}, av[4][4] = {};
#pragma unroll 8
    for (int k = 0; k < 64; k++) {
        float4 a = *(const float4*)&As[k][ty * 4];
        float4 u = *(const float4*)&Wa[k][tx * 4];
        float4 d = *(const float4*)&Wd[k][tx * 4];
        au[0][0] += a.x * u.x; au[0][1] += a.x * u.y; au[0][2] += a.x * u.z; au[0][3] += a.x * u.w;
        au[1][0] += a.y * u.x; au[1][1] += a.y * u.y; au[1][2] += a.y * u.z; au[1][3] += a.y * u.w;
        au[2][0] += a.z * u.x; au[2][1] += a.z * u.y; au[2][2] += a.z * u.z; au[2][3] += a.z * u.w;
        au[3][0] += a.w * u.x; au[3][1] += a.w * u.y; au[3][2] += a.w * u.z; au[3][3] += a.w * u.w;
        av[0][0] += a.x * d.x; av[0][1] += a.x * d.y; av[0][2] += a.x * d.z; av[0][3] += a.x * d.w;
        av[1][0] += a.y * d.x; av[1][1] += a.y * d.y; av[1][2] += a.y * d.z; av[1][3] += a.y * d.w;
        av[2][0] += a.z * d.x; av[2][1] += a.z * d.y; av[2][2] += a.z * d.z; av[2][3] += a.z * d.w;
        av[3][0] += a.w * d.x; av[3][1] += a.w * d.y; av[3][2] += a.w * d.z; av[3][3] += a.w * d.w;
    }
#pragma unroll
    for (int j = 0; j < 4; j++) {
        int o = tx * 4 + j;
        float sc = sv[o], bi = bv[o];
#pragma unroll
        for (int i = 0; i < 4; i++) {
            size_t rr = rowBase + ty * 4 + i;
            U[rr * 64 + o] = au[i][j] * sc;
            V[rr * 64 + o] = av[i][j] * sc + bi;
        }
    }
}

// ---------------------------------------------------------------------------
// gemm2gf: layer-2 GEMM (FFMA2 inner loop) with fused gather-A and max-over-k.
// ---------------------------------------------------------------------------
__global__ __launch_bounds__(256) void gemm2gf_kernel(
    const float* __restrict__ U, const float* __restrict__ Vv,
    const int* __restrict__ idx, const float* __restrict__ W,
    const float* __restrict__ sv, const float* __restrict__ bv,
    float* __restrict__ cat, int off)
{
    __shared__ __align__(16) float As[64][68];
    __shared__ __align__(16) float Ws[64][68];
    int tid = threadIdx.x;
    int i0 = blockIdx.x * 3;
    int r = tid >> 2, q0 = (tid & 3) * 4;
    {
        int i = i0 + r / 20;
        if (i >= BB * NN) i = BB * NN - 1;
        int p = i * 20 + (r % 20);
        int j = idx[p];
        int rbase = (i >> 12) << 12;
        const float4* urow = (const float4*)&U[(size_t)(rbase + j) * 64];
        const float4* vrow = (const float4*)&Vv[(size_t)i * 64];
#pragma unroll
        for (int q = q0; q < q0 + 4; q++) {
            float4 u = urow[q], v = vrow[q];
            As[q * 4 + 0][r] = lrelu(u.x + v.x);
            As[q * 4 + 1][r] = lrelu(u.y + v.y);
            As[q * 4 + 2][r] = lrelu(u.z + v.z);
            As[q * 4 + 3][r] = lrelu(u.w + v.w);
            float4 w4 = *(const float4*)&W[r * 64 + q * 4];
            Ws[q * 4 + 0][r] = w4.x; Ws[q * 4 + 1][r] = w4.y;
            Ws[q * 4 + 2][r] = w4.z; Ws[q * 4 + 3][r] = w4.w;
        }
    }
    __syncthreads();
    int ty = tid >> 4, tx = tid & 15;
    uint32_t wsB = (uint32_t)__cvta_generic_to_shared(&Ws[0][0]);
    unsigned long long accp[4][2] = {};
#pragma unroll 16
    for (int k = 0; k < 64; k++) {
        float4 a = *(const float4*)&As[k][ty * 4];
        unsigned long long wlo, whi;
        asm("ld.shared.v2.b64 {%0,%1}, [%2];"
            : "=l"(wlo), "=l"(whi) : "r"(wsB + (uint32_t)((k * 68 + tx * 4) * 4)));
        unsigned long long ax, ay, az, aw;
        asm("mov.b64 %0, {%1,%1};" : "=l"(ax) : "f"(a.x));
        asm("mov.b64 %0, {%1,%1};" : "=l"(ay) : "f"(a.y));
        asm("mov.b64 %0, {%1,%1};" : "=l"(az) : "f"(a.z));
        asm("mov.b64 %0, {%1,%1};" : "=l"(aw) : "f"(a.w));
        asm("fma.rn.f32x2 %0, %1, %2, %0;" : "+l"(accp[0][0]) : "l"(ax), "l"(wlo));
        asm("fma.rn.f32x2 %0, %1, %2, %0;" : "+l"(accp[0][1]) : "l"(ax), "l"(whi));
        asm("fma.rn.f32x2 %0, %1, %2, %0;" : "+l"(accp[1][0]) : "l"(ay), "l"(wlo));
        asm("fma.rn.f32x2 %0, %1, %2, %0;" : "+l"(accp[1][1]) : "l"(ay), "l"(whi));
        asm("fma.rn.f32x2 %0, %1, %2, %0;" : "+l"(accp[2][0]) : "l"(az), "l"(wlo));
        asm("fma.rn.f32x2 %0, %1, %2, %0;" : "+l"(accp[2][1]) : "l"(az), "l"(whi));
        asm("fma.rn.f32x2 %0, %1, %2, %0;" : "+l"(accp[3][0]) : "l"(aw), "l"(wlo));
        asm("fma.rn.f32x2 %0, %1, %2, %0;" : "+l"(accp[3][1]) : "l"(aw), "l"(whi));
    }
    float acc[4][4];
#pragma unroll
    for (int i = 0; i < 4; i++) {
        asm("mov.b64 {%0,%1}, %2;" : "=f"(acc[i][0]), "=f"(acc[i][1]) : "l"(accp[i][0]));
        asm("mov.b64 {%0,%1}, %2;" : "=f"(acc[i][2]), "=f"(acc[i][3]) : "l"(accp[i][1]));
    }

    float sc0 = sv[tx * 4 + 0], sc1 = sv[tx * 4 + 1], sc2 = sv[tx * 4 + 2], sc3 = sv[tx * 4 + 3];
    float bi0 = bv[tx * 4 + 0], bi1 = bv[tx * 4 + 1], bi2 = bv[tx * 4 + 2], bi3 = bv[tx * 4 + 3];
    __syncthreads();
#pragma unroll
    for (int i2 = 0; i2 < 4; i2++) {
        float4 vv;
        vv.x = lrelu(acc[i2][0] * sc0 + bi0);
        vv.y = lrelu(acc[i2][1] * sc1 + bi1);
        vv.z = lrelu(acc[i2][2] * sc2 + bi2);
        vv.w = lrelu(acc[i2][3] * sc3 + bi3);
        *(float4*)&As[ty * 4 + i2][tx * 4] = vv;
    }
    __syncthreads();
    if (tid < 192) {
        int pp = tid >> 6, o = tid & 63;
        int i = i0 + pp;
        if (i < BB * NN) {
            float m = As[pp * 20][o];
#pragma unroll
            for (int kk = 1; kk < KNBR; kk++)
                m = fmaxf(m, As[pp * 20 + kk][o]);
            cat[(size_t)i * 192 + off + o] = m;
        }
    }
}

// ---------------------------------------------------------------------------
// Stage-3 fused: out = max_k lrelu(U'[idx] + V'[i])
// ---------------------------------------------------------------------------
__global__ __launch_bounds__(256) void stage3_kernel(
    const float* __restrict__ U, const float* __restrict__ Vv,
    const int* __restrict__ idx, float* __restrict__ out)
{
    int tid = threadIdx.x, warp = tid >> 5, lane = tid & 31;
    int i = blockIdx.x * 8 + warp;
    int rbase = (i >> 12) << 12;
    float v0 = Vv[(size_t)i * 64 + lane];
    float v1 = Vv[(size_t)i * 64 + lane + 32];
    float m0 = -CUDART_INF_F, m1 = -CUDART_INF_F;
#pragma unroll
    for (int k = 0; k < KNBR; k++) {
        int j = idx[i * KNBR + k];
        const float* ur = &U[(size_t)(rbase + j) * 64];
        m0 = fmaxf(m0, lrelu(ur[lane] + v0));
        m1 = fmaxf(m1, lrelu(ur[lane + 32] + v1));
    }
    out[(size_t)i * 192 + 128 + lane] = m0;
    out[(size_t)i * 192 + 128 + lane + 32] = m1;
}

// ---------------------------------------------------------------------------
// Tiled fp32 GEMM (FFMA2 inner loop): 64x64x16 tiles, 4x4/thread.
// MODE 0 row-major float4 store; MODE 1 transposed final store;
// MODE 2 leaky+col-max (smem-reduced) -> single atomicMax per column.
// ---------------------------------------------------------------------------
template <int MODE, bool SB, bool EXT, bool LEAKY>
__global__ __launch_bounds__(256) void gemm_kernel(
    const float* __restrict__ A, int lda,
    const float* __restrict__ W, int ldw, int woff,
    const float* __restrict__ sv, const float* __restrict__ bv,
    const float* __restrict__ ext,
    float* __restrict__ outp, unsigned* __restrict__ gout,
    int Nout, int Ktot)
{
    __shared__ __align__(16) float As[16][68];
    __shared__ __align__(16) float Ws[16][68];
    __shared__ float cm[16][65];

    int tid = threadIdx.x;
    int tx = tid & 15, ty = tid >> 4;
    int rowBase = blockIdx.y * 64, colBase = blockIdx.x * 64;
    int lr = tid >> 2, lk = tid & 3;
    uint32_t wsB = (uint32_t)__cvta_generic_to_shared(&Ws[0][0]);

    unsigned long long accp[4][2] = {};

    for (int k0 = 0; k0 < Ktot; k0 += 16) {
        float4 av = *(const float4*)&A[(size_t)(rowBase + lr) * lda + k0 + lk * 4];
        float4 wv = make_float4(0.f, 0.f, 0.f, 0.f);
        if (colBase + lr < Nout)
            wv = *(const float4*)&W[(size_t)(colBase + lr) * ldw + woff + k0 + lk * 4];
        __syncthreads();
        As[lk * 4 + 0][lr] = av.x; As[lk * 4 + 1][lr] = av.y;
        As[lk * 4 + 2][lr] = av.z; As[lk * 4 + 3][lr] = av.w;
        Ws[lk * 4 + 0][lr] = wv.x; Ws[lk * 4 + 1][lr] = wv.y;
        Ws[lk * 4 + 2][lr] = wv.z; Ws[lk * 4 + 3][lr] = wv.w;
        __syncthreads();
#pragma unroll
        for (int k = 0; k < 16; k++) {
            float4 a = *(const float4*)&As[k][ty * 4];
            unsigned long long wlo, whi;
            asm("ld.shared.v2.b64 {%0,%1}, [%2];"
                : "=l"(wlo), "=l"(whi) : "r"(wsB + (uint32_t)((k * 68 + tx * 4) * 4)));
            unsigned long long ax, ay, az, aw;
            asm("mov.b64 %0, {%1,%1};" : "=l"(ax) : "f"(a.x));
            asm("mov.b64 %0, {%1,%1};" : "=l"(ay) : "f"(a.y));
            asm("mov.b64 %0, {%1,%1};" : "=l"(az) : "f"(a.z));
            asm("mov.b64 %0, {%1,%1};" : "=l"(aw) : "f"(a.w));
            asm("fma.rn.f32x2 %0, %1, %2, %0;" : "+l"(accp[0][0]) : "l"(ax), "l"(wlo));
            asm("fma.rn.f32x2 %0, %1, %2, %0;" : "+l"(accp[0][1]) : "l"(ax), "l"(whi));
            asm("fma.rn.f32x2 %0, %1, %2, %0;" : "+l"(accp[1][0]) : "l"(ay), "l"(wlo));
            asm("fma.rn.f32x2 %0, %1, %2, %0;" : "+l"(accp[1][1]) : "l"(ay), "l"(whi));
            asm("fma.rn.f32x2 %0, %1, %2, %0;" : "+l"(accp[2][0]) : "l"(az), "l"(wlo));
            asm("fma.rn.f32x2 %0, %1, %2, %0;" : "+l"(accp[2][1]) : "l"(az), "l"(whi));
            asm("fma.rn.f32x2 %0, %1, %2, %0;" : "+l"(accp[3][0]) : "l"(aw), "l"(wlo));
            asm("fma.rn.f32x2 %0, %1, %2, %0;" : "+l"(accp[3][1]) : "l"(aw), "l"(whi));
        }
    }

    float acc[4][4];
#pragma unroll
    for (int i = 0; i < 4; i++) {
        asm("mov.b64 {%0,%1}, %2;" : "=f"(acc[i][0]), "=f"(acc[i][1]) : "l"(accp[i][0]));
        asm("mov.b64 {%0,%1}, %2;" : "=f"(acc[i][2]), "=f"(acc[i][3]) : "l"(accp[i][1]));
    }

    int bidx = rowBase >> 12;

    if (MODE == 2) {
#pragma unroll
        for (int j = 0; j < 4; j++) {
            int o = colBase + tx * 4 + j;
            float sc = SB ? sv[o] : 1.f;
            float bi = SB ? bv[o] : 0.f;
            float m = -CUDART_INF_F;
#pragma unroll
            for (int i = 0; i < 4; i++) {
                float v = acc[i][j];
                if (SB) v = v * sc + bi;
                if (LEAKY) v = lrelu(v);
                m = fmaxf(m, v);
            }
            cm[ty][tx * 4 + j] = m;
        }
        __syncthreads();
        if (tid < 64) {
            float mm = cm[0][tid];
#pragma unroll
            for (int t = 1; t < 16; t++) mm = fmaxf(mm, cm[t][tid]);
            atomicMax(&gout[bidx * DIMG + colBase + tid], encf(mm));
        }
    } else if (MODE == 0) {
        float sc[4], bi[4], ex[4];
#pragma unroll
        for (int j = 0; j < 4; j++) {
            int o = colBase + tx * 4 + j;
            sc[j] = SB ? sv[o] : 1.f;
            bi[j] = SB ? bv[o] : 0.f;
            ex[j] = EXT ? ext[bidx * Nout + o] : 0.f;
        }
#pragma unroll
        for (int i = 0; i < 4; i++) {
            int r = rowBase + ty * 4 + i;
            float4 vv;
            float v0 = acc[i][0], v1 = acc[i][1], v2 = acc[i][2], v3 = acc[i][3];
            if (EXT) { v0 += ex[0]; v1 += ex[1]; v2 += ex[2]; v3 += ex[3]; }
            if (SB)  { v0 = v0 * sc[0] + bi[0]; v1 = v1 * sc[1] + bi[1];
                       v2 = v2 * sc[2] + bi[2]; v3 = v3 * sc[3] + bi[3]; }
            if (LEAKY) { v0 = lrelu(v0); v1 = lrelu(v1); v2 = lrelu(v2); v3 = lrelu(v3); }
            vv.x = v0; vv.y = v1; vv.z = v2; vv.w = v3;
            *(float4*)&outp[(size_t)r * Nout + colBase + tx * 4] = vv;
        }
    } else {
#pragma unroll
        for (int j = 0; j < 4; j++) {
            int o = colBase + tx * 4 + j;
#pragma unroll
            for (int i = 0; i < 4; i++) {
                int r = rowBase + ty * 4 + i;
                if (o < 13)
                    outp[((size_t)bidx * 13 + o) * NN + (r & (NN - 1))] = acc[i][j];
            }
        }
    }
}

// ---------------------------------------------------------------------------
// g-buffer init + gdot = w8[:, :1024] @ g  (per batch)
// ---------------------------------------------------------------------------
__global__ void zero_gu_kernel(unsigned* __restrict__ gu) {
    int t = blockIdx.x * blockDim.x + threadIdx.x;
    if (t < BB * DIMG) gu[t] = 0u;
}

__global__ __launch_bounds__(256) void gdot_kernel(
    const unsigned* __restrict__ gu, const float* __restrict__ w8, float* __restrict__ gdot)
{
    int b = blockIdx.x;
    __shared__ float gsh[DIMG];
    for (int i = threadIdx.x; i < DIMG; i += blockDim.x) gsh[i] = decf(gu[b * DIMG + i]);
    __syncthreads();
    int warp = threadIdx.x >> 5, lane = threadIdx.x & 31;
    for (int o = warp * 32; o < warp * 32 + 32; o++) {
        float accv = 0.f;
        for (int c = lane; c < DIMG; c += 32)
            accv += w8[(size_t)o * 1216 + c] * gsh[c];
#pragma unroll
        for (int off = 16; off; off >>= 1)
            accv += __shfl_down_sync(0xffffffffu, accv, off);
        if (lane == 0) gdot[b * 256 + o] = accv;
    }
}

// ---------------------------------------------------------------------------
// Launcher
// ---------------------------------------------------------------------------
extern "C" void kernel_launch(void* const* d_in, const int* in_sizes, int n_in,
                              void* d_out, int out_size)
{
    (void)in_sizes; (void)n_in; (void)out_size;

    const float* x   = (const float*)d_in[0];
    const float* w1  = (const float*)d_in[1];
    const float* s1  = (const float*)d_in[2];
    const float* b1  = (const float*)d_in[3];
    const float* w2  = (const float*)d_in[4];
    const float* s2  = (const float*)d_in[5];
    const float* b2  = (const float*)d_in[6];
    const float* w3  = (const float*)d_in[7];
    const float* s3  = (const float*)d_in[8];
    const float* b3  = (const float*)d_in[9];
    const float* w4  = (const float*)d_in[10];
    const float* s4  = (const float*)d_in[11];
    const float* b4  = (const float*)d_in[12];
    const float* w5  = (const float*)d_in[13];
    const float* s5  = (const float*)d_in[14];
    const float* b5  = (const float*)d_in[15];
    const float* w6  = (const float*)d_in[16];
    const float* s6  = (const float*)d_in[17];
    const float* b6  = (const float*)d_in[18];
    const float* w8  = (const float*)d_in[19];
    const float* s8  = (const float*)d_in[20];
    const float* b8  = (const float*)d_in[21];
    const float* w9  = (const float*)d_in[22];
    const float* s9  = (const float*)d_in[23];
    const float* b9  = (const float*)d_in[24];
    const float* w10 = (const float*)d_in[25];
    const float* s10 = (const float*)d_in[26];
    const float* b10 = (const float*)d_in[27];
    const float* w11 = (const float*)d_in[28];
    float* out = (float*)d_out;

    void* p;
    cudaGetSymbolAddress(&p, d_cat);   float*    cat   = (float*)p;
    cudaGetSymbolAddress(&p, d_idx);   int*      idx   = (int*)p;
    cudaGetSymbolAddress(&p, d_gu);    unsigned* gu    = (unsigned*)p;
    cudaGetSymbolAddress(&p, d_gdot);  float*    gdot  = (float*)p;
    cudaGetSymbolAddress(&p, d_h8);    float*    h8    = (float*)p;
    cudaGetSymbolAddress(&p, d_h9);    float*    h9    = (float*)p;
    cudaGetSymbolAddress(&p, d_h10);   float*    h10   = (float*)p;
    cudaGetSymbolAddress(&p, d_U);     float*    U     = (float*)p;
    cudaGetSymbolAddress(&p, d_V);     float*    V     = (float*)p;
    cudaGetSymbolAddress(&p, d_xx);    float*    xxb   = (float*)p;

    const int uvSmem = 3 * 64 * 68 * 4;   // 52224
    cudaFuncSetAttribute((const void*)uv64_kernel,
                         cudaFuncAttributeMaxDynamicSharedMemorySize, uvSmem);

    const int PTS = BB * NN;                 // 32768
    const int G2F = (PTS + 2) / 3;
    dim3 knnGrid(NN / 128, BB);

    // stage 1 (3 -> 64 -> 64)
    knn3_kernel<<<knnGrid, 128>>>(x, idx);
    uv3_kernel<<<PTS / 8, 256>>>(x, w1, s1, b1, U, V);
    gemm2gf_kernel<<<G2F, 256>>>(U, V, idx, w2, s2, b2, cat, 0);

    // stage 2 (64 -> 64 -> 64)
    xx_kernel<<<PTS / 256, 256>>>(cat + 0, 192, xxb);
    knn64_kernel<<<knnGrid, 128>>>(cat + 0, 192, xxb, idx);
    uv64_kernel<<<PTS / 64, 256, uvSmem>>>(cat + 0, 192, w3, s3, b3, U, V);
    gemm2gf_kernel<<<G2F, 256>>>(U, V, idx, w4, s4, b4, cat, 64);

    // stage 3 (64 -> 64, single layer, fully fused)
    xx_kernel<<<PTS / 256, 256>>>(cat + 64, 192, xxb);
    knn64_kernel<<<knnGrid, 128>>>(cat + 64, 192, xxb, idx);
    uv64_kernel<<<PTS / 64, 256, uvSmem>>>(cat + 64, 192, w5, s5, b5, U, V);
    stage3_kernel<<<PTS / 8, 256>>>(U, V, idx, cat);

    // cbl6 (192 -> 1024) fused with max-over-N (smem-reduced atomics)
    zero_gu_kernel<<<(BB * DIMG + 255) / 256, 256>>>(gu);
    gemm_kernel<2, true, false, true><<<dim3(DIMG / 64, PTS / 64), 256>>>(
        cat, 192, w6, 192, 0, s6, b6, nullptr, nullptr, gu, DIMG, 192);

    // gdot[b,o] = w8[o, :1024] . g[b]
    gdot_kernel<<<BB, 256>>>(gu, w8, gdot);

    // cbl8: (gdot + w8[:,1024:] @ cat) * s8 + b8, leaky
    gemm_kernel<0, true, true, true><<<dim3(256 / 64, PTS / 64), 256>>>(
        cat, 192, w8, 1216, 1024, s8, b8, gdot, h8, nullptr, 256, 192);

    // cbl9
    gemm_kernel<0, true, false, true><<<dim3(256 / 64, PTS / 64), 256>>>(
        h8, 256, w9, 256, 0, s9, b9, nullptr, h9, nullptr, 256, 256);

    // cbl10
    gemm_kernel<0, true, false, true><<<dim3(128 / 64, PTS / 64), 256>>>(
        h9, 256, w10, 256, 0, s10, b10, nullptr, h10, nullptr, 128, 256);

    // classifier + transpose to (B,13,N)
    gemm_kernel<1, false, false, false><<<dim3(1, PTS / 64), 256>>>(
        h10, 128, w11, 128, 0, nullptr, nullptr, nullptr, out, nullptr, 13, 128);
}

// round 17
// speedup vs baseline: 2.0962x; 1.0055x over previous
#include <cuda_runtime.h>
#include <cuda_bf16.h>
#include <math_constants.h>
#include <cstdint>

#define BB 8
#define NN 4096
#define KNBR 20
#define DIMG 1024

// ---------------------------------------------------------------------------
// Scratch (device globals; no allocations allowed)
// ---------------------------------------------------------------------------
__device__ float    d_cat  [BB * NN * 192];
__device__ int      d_idx  [BB * NN * KNBR];
__device__ unsigned d_gu   [BB * DIMG];
__device__ float    d_gdot [BB * 256];
__device__ float    d_h8   [BB * NN * 256];
__device__ float    d_h9   [BB * NN * 256];
__device__ float    d_h10  [BB * NN * 128];
__device__ float    d_U    [BB * NN * 64];
__device__ float    d_V    [BB * NN * 64];
__device__ float    d_xx   [BB * NN];

__device__ __forceinline__ float lrelu(float y) { return y > 0.f ? y : 0.2f * y; }

__device__ __forceinline__ unsigned encf(float v) {
    unsigned u = __float_as_uint(v);
    return (u & 0x80000000u) ? ~u : (u | 0x80000000u);
}
__device__ __forceinline__ float decf(unsigned u) {
    return __uint_as_float((u & 0x80000000u) ? (u & 0x7fffffffu) : ~u);
}

__device__ __forceinline__ void cp_async16(uint32_t saddr, const void* g) {
    asm volatile("cp.async.cg.shared.global [%0], [%1], 16;"
                 :: "r"(saddr), "l"(g));
}

// Fully-unrolled register-resident top-K insertion (strict value order).
__device__ __forceinline__ void topk_insert(
    float (&tv)[KNBR], int (&ti)[KNBR], float v, int ii)
{
#pragma unroll
    for (int t = KNBR - 1; t >= 0; t--) {
        if (t == 0 || v <= tv[t - 1]) { tv[t] = v; ti[t] = ii; break; }
        tv[t] = tv[t - 1]; ti[t] = ti[t - 1];
    }
}

// Exact xx arithmetic shared by producer (fused epilogue) and consumer (knn64):
// per 16-channel block, even-lane fmaf chain + odd-lane fmaf chain (ascending),
// block sums combined pairwise — matches the packed-FFMA2 dot lane-for-lane,
// so self-distance is exactly 0.
__device__ __forceinline__ float xx_exact(const float* __restrict__ r) {
    float d[4];
#pragma unroll
    for (int blk = 0; blk < 4; blk++) {
        float lo = 0.f, hi = 0.f;
#pragma unroll
        for (int p = 0; p < 8; p++) {
            float e = r[blk * 16 + p * 2];
            float o = r[blk * 16 + p * 2 + 1];
            lo = fmaf(e, e, lo);
            hi = fmaf(o, o, hi);
        }
        d[blk] = lo + hi;
    }
    return (d[0] + d[1]) + (d[2] + d[3]);
}

// ---------------------------------------------------------------------------
// KNN, C=3 : thread per row, reads x (B,3,N) directly
// ---------------------------------------------------------------------------
__global__ __launch_bounds__(128) void knn3_kernel(
    const float* __restrict__ x, int* __restrict__ idxo)
{
    const int TT = 64;
    int b = blockIdx.y;
    int n = blockIdx.x * blockDim.x + threadIdx.x;
    const float* base = x + (size_t)b * 3 * NN;

    float f0 = base[n];
    float f1 = base[NN + n];
    float f2 = base[2 * NN + n];
    float my2 = f0 * f0 + f1 * f1 + f2 * f2;

    float topv[KNBR]; int topi[KNBR];
#pragma unroll
    for (int i = 0; i < KNBR; i++) { topv[i] = -CUDART_INF_F; topi[i] = 0; }
    float thr = -CUDART_INF_F;

    __shared__ float tile[TT * 3];
    __shared__ float txx[TT];

    for (int m0 = 0; m0 < NN; m0 += TT) {
        __syncthreads();
        for (int e = threadIdx.x; e < TT * 3; e += blockDim.x) {
            int c = e >> 6, j = e & 63;
            tile[j * 3 + c] = base[c * NN + m0 + j];
        }
        __syncthreads();
        if (threadIdx.x < TT) {
            float a = tile[threadIdx.x * 3 + 0];
            float bq = tile[threadIdx.x * 3 + 1];
            float cq = tile[threadIdx.x * 3 + 2];
            txx[threadIdx.x] = a * a + bq * bq + cq * cq;
        }
        __syncthreads();
#pragma unroll 4
        for (int j = 0; j < TT; j++) {
            float dot = f0 * tile[j * 3 + 0] + f1 * tile[j * 3 + 1] + f2 * tile[j * 3 + 2];
            float v = 2.0f * dot - my2 - txx[j];
            if (v > thr) {
                topk_insert(topv, topi, v, m0 + j);
                thr = topv[KNBR - 1];
            }
        }
    }
    int* op = idxo + ((size_t)b * NN + n) * KNBR;
#pragma unroll
    for (int i = 0; i < KNBR; i++) op[i] = topi[i];
}

// ---------------------------------------------------------------------------
// KNN, C=64 : thread-per-row, cp.async double-buffered 64-candidate tiles,
// packed fma.rn.f32x2 dot (32 FFMA2/candidate), register-resident top-20.
// One sync per tile (bottom sync proven redundant in R15).
// ---------------------------------------------------------------------------
__global__ __launch_bounds__(128) void knn64_kernel(
    const float* __restrict__ feat, int stride, const float* __restrict__ xxg,
    int* __restrict__ idxo)
{
    const int TT = 64;
    const int C = 64;
    int b = blockIdx.y;
    int n = blockIdx.x * blockDim.x + threadIdx.x;
    const float* base = feat + (size_t)b * NN * stride;
    const float* xb = xxg + (size_t)b * NN;

    // load query row and pack into 32 f32x2 registers (once per row)
    unsigned long long qp[32];
#pragma unroll
    for (int q = 0; q < 16; q++) {
        float4 v = *(const float4*)&base[(size_t)n * stride + q * 4];
        asm("mov.b64 %0, {%1,%2};" : "=l"(qp[2 * q])     : "f"(v.x), "f"(v.y));
        asm("mov.b64 %0, {%1,%2};" : "=l"(qp[2 * q + 1]) : "f"(v.z), "f"(v.w));
    }
    float my2 = xb[n];

    float topv[KNBR]; int topi[KNBR];
#pragma unroll
    for (int i = 0; i < KNBR; i++) { topv[i] = -CUDART_INF_F; topi[i] = 0; }
    float thr = -CUDART_INF_F;

    __shared__ __align__(16) float tile[2][TT * C];
    __shared__ __align__(16) float cxx[2][TT];

    uint32_t sb0 = (uint32_t)__cvta_generic_to_shared(&tile[0][0]);
    uint32_t sc0 = (uint32_t)__cvta_generic_to_shared(&cxx[0][0]);
    int tid = threadIdx.x;

    auto issue = [&](int ct) {
        int bf = ct & 1;
        int m0 = ct * TT;
        uint32_t sb = sb0 + bf * (TT * C * 4);
#pragma unroll
        for (int m = 0; m < 8; m++) {
            int idx4 = tid + m * 128;
            int j = idx4 >> 4, q = idx4 & 15;
            cp_async16(sb + (uint32_t)(j * C + q * 4) * 4,
                       &base[(size_t)(m0 + j) * stride + q * 4]);
        }
        if (tid < 16)
            cp_async16(sc0 + (uint32_t)(bf * TT + tid * 4) * 4, &xb[m0 + tid * 4]);
        asm volatile("cp.async.commit_group;");
    };

    issue(0);

    for (int ct = 0; ct < NN / TT; ct++) {
        asm volatile("cp.async.wait_group 0;");
        __syncthreads();                     // loads visible; prev compute done
        if (ct < NN / TT - 1) issue(ct + 1); // overlap next load w/ compute

        uint32_t tbase = sb0 + (ct & 1) * (TT * C * 4);
        const float* cx = cxx[ct & 1];
        int m0 = ct * TT;
#pragma unroll 2
        for (int j = 0; j < TT; j++) {
            uint32_t taddr = tbase + (uint32_t)(j * C) * 4;
            unsigned long long a0 = 0ull, a1 = 0ull, a2 = 0ull, a3 = 0ull;
#pragma unroll
            for (int m = 0; m < 4; m++) {
                unsigned long long c0, c1, c2, c3;
                asm("ld.shared.v2.b64 {%0,%1}, [%2];"
                    : "=l"(c0), "=l"(c1) : "r"(taddr + m * 64 + 0));
                asm("ld.shared.v2.b64 {%0,%1}, [%2];"
                    : "=l"(c2), "=l"(c3) : "r"(taddr + m * 64 + 16));
                unsigned long long c4, c5, c6, c7;
                asm("ld.shared.v2.b64 {%0,%1}, [%2];"
                    : "=l"(c4), "=l"(c5) : "r"(taddr + m * 64 + 32));
                asm("ld.shared.v2.b64 {%0,%1}, [%2];"
                    : "=l"(c6), "=l"(c7) : "r"(taddr + m * 64 + 48));
                unsigned long long* ap = (m == 0) ? &a0 : (m == 1) ? &a1 : (m == 2) ? &a2 : &a3;
                asm("fma.rn.f32x2 %0, %1, %2, %0;" : "+l"(*ap) : "l"(qp[m * 8 + 0]), "l"(c0));
                asm("fma.rn.f32x2 %0, %1, %2, %0;" : "+l"(*ap) : "l"(qp[m * 8 + 1]), "l"(c1));
                asm("fma.rn.f32x2 %0, %1, %2, %0;" : "+l"(*ap) : "l"(qp[m * 8 + 2]), "l"(c2));
                asm("fma.rn.f32x2 %0, %1, %2, %0;" : "+l"(*ap) : "l"(qp[m * 8 + 3]), "l"(c3));
                asm("fma.rn.f32x2 %0, %1, %2, %0;" : "+l"(*ap) : "l"(qp[m * 8 + 4]), "l"(c4));
                asm("fma.rn.f32x2 %0, %1, %2, %0;" : "+l"(*ap) : "l"(qp[m * 8 + 5]), "l"(c5));
                asm("fma.rn.f32x2 %0, %1, %2, %0;" : "+l"(*ap) : "l"(qp[m * 8 + 6]), "l"(c6));
                asm("fma.rn.f32x2 %0, %1, %2, %0;" : "+l"(*ap) : "l"(qp[m * 8 + 7]), "l"(c7));
            }
            float lA, hA, lB, hB, lC, hC, lD, hD;
            asm("mov.b64 {%0,%1}, %2;" : "=f"(lA), "=f"(hA) : "l"(a0));
            asm("mov.b64 {%0,%1}, %2;" : "=f"(lB), "=f"(hB) : "l"(a1));
            asm("mov.b64 {%0,%1}, %2;" : "=f"(lC), "=f"(hC) : "l"(a2));
            asm("mov.b64 {%0,%1}, %2;" : "=f"(lD), "=f"(hD) : "l"(a3));
            float dA = lA + hA, dB = lB + hB, dC = lC + hC, dD = lD + hD;
            float v = 2.0f * ((dA + dB) + (dC + dD)) - my2 - cx[j];
            if (v > thr) {
                topk_insert(topv, topi, v, m0 + j);
                thr = topv[KNBR - 1];
            }
        }
        // no bottom sync: next iteration's top sync provides the ordering
    }
    int* op = idxo + ((size_t)b * NN + n) * KNBR;
#pragma unroll
    for (int i = 0; i < KNBR; i++) op[i] = topi[i];
}

// ---------------------------------------------------------------------------
// Stage-1 U'/V' (CIN=3), reads x (B,3,N) directly
// ---------------------------------------------------------------------------
__global__ __launch_bounds__(256) void uv3_kernel(
    const float* __restrict__ x, const float* __restrict__ w,
    const float* __restrict__ sv, const float* __restrict__ bv,
    float* __restrict__ U, float* __restrict__ V)
{
    __shared__ float wa[64 * 3], wd[64 * 3], ss[64], bb[64];
    int tid = threadIdx.x;
    if (tid < 64) {
#pragma unroll
        for (int c = 0; c < 3; c++) {
            wa[tid * 3 + c] = w[tid * 6 + c];
            wd[tid * 3 + c] = w[tid * 6 + 3 + c] - w[tid * 6 + c];
        }
        ss[tid] = sv[tid]; bb[tid] = bv[tid];
    }
    __syncthreads();
    int warp = tid >> 5, lane = tid & 31;
    int i = blockIdx.x * 8 + warp;
    int b = i >> 12, n = i & (NN - 1);
    const float* bx = x + (size_t)b * 3 * NN;
    float x0 = bx[n], x1 = bx[NN + n], x2 = bx[2 * NN + n];
#pragma unroll
    for (int h = 0; h < 2; h++) {
        int o = lane + h * 32;
        float u = ss[o] * (wa[o * 3] * x0 + wa[o * 3 + 1] * x1 + wa[o * 3 + 2] * x2);
        float v = ss[o] * (wd[o * 3] * x0 + wd[o * 3 + 1] * x1 + wd[o * 3 + 2] * x2) + bb[o];
        U[(size_t)i * 64 + o] = u;
        V[(size_t)i * 64 + o] = v;
    }
}

// ---------------------------------------------------------------------------
// uv64: one-shot K=64 dual GEMM (wdiff folded)
// ---------------------------------------------------------------------------
__global__ __launch_bounds__(256) void uv64_kernel(
    const float* __restrict__ A, int lda,
    const float* __restrict__ w,
    const float* __restrict__ sv, const float* __restrict__ bv,
    float* __restrict__ U, float* __restrict__ V)
{
    extern __shared__ float sm[];
    float (*As)[68] = (float(*)[68])sm;
    float (*Wa)[68] = (float(*)[68])(sm + 64 * 68);
    float (*Wd)[68] = (float(*)[68])(sm + 2 * 64 * 68);

    int tid = threadIdx.x;
    int rowBase = blockIdx.x * 64;
    int r = tid >> 2, q0 = (tid & 3) * 4;

#pragma unroll
    for (int q = q0; q < q0 + 4; q++) {
        float4 a4 = *(const float4*)&A[(size_t)(rowBase + r) * lda + q * 4];
        As[q * 4 + 0][r] = a4.x; As[q * 4 + 1][r] = a4.y;
        As[q * 4 + 2][r] = a4.z; As[q * 4 + 3][r] = a4.w;
        float4 wa4 = *(const float4*)&w[r * 128 + q * 4];
        float4 wb4 = *(const float4*)&w[r * 128 + 64 + q * 4];
        Wa[q * 4 + 0][r] = wa4.x; Wa[q * 4 + 1][r] = wa4.y;
        Wa[q * 4 + 2][r] = wa4.z; Wa[q * 4 + 3][r] = wa4.w;
        Wd[q * 4 + 0][r] = wb4.x - wa4.x; Wd[q * 4 + 1][r] = wb4.y - wa4.y;
        Wd[q * 4 + 2][r] = wb4.z - wa4.z; Wd[q * 4 + 3][r] = wb4.w - wa4.w;
    }
    __syncthreads();

    int ty = tid >> 4, tx = tid & 15;
    float au[4][4] = {}, av[4][4] = {};
#pragma unroll 8
    for (int k = 0; k < 64; k++) {
        float4 a = *(const float4*)&As[k][ty * 4];
        float4 u = *(const float4*)&Wa[k][tx * 4];
        float4 d = *(const float4*)&Wd[k][tx * 4];
        au[0][0] += a.x * u.x; au[0][1] += a.x * u.y; au[0][2] += a.x * u.z; au[0][3] += a.x * u.w;
        au[1][0] += a.y * u.x; au[1][1] += a.y * u.y; au[1][2] += a.y * u.z; au[1][3] += a.y * u.w;
        au[2][0] += a.z * u.x; au[2][1] += a.z * u.y; au[2][2] += a.z * u.z; au[2][3] += a.z * u.w;
        au[3][0] += a.w * u.x; au[3][1] += a.w * u.y; au[3][2] += a.w * u.z; au[3][3] += a.w * u.w;
        av[0][0] += a.x * d.x; av[0][1] += a.x * d.y; av[0][2] += a.x * d.z; av[0][3] += a.x * d.w;
        av[1][0] += a.y * d.x; av[1][1] += a.y * d.y; av[1][2] += a.y * d.z; av[1][3] += a.y * d.w;
        av[2][0] += a.z * d.x; av[2][1] += a.z * d.y; av[2][2] += a.z * d.z; av[2][3] += a.z * d.w;
        av[3][0] += a.w * d.x; av[3][1] += a.w * d.y; av[3][2] += a.w * d.z; av[3][3] += a.w * d.w;
    }
#pragma unroll
    for (int j = 0; j < 4; j++) {
        int o = tx * 4 + j;
        float sc = sv[o], bi = bv[o];
#pragma unroll
        for (int i = 0; i < 4; i++) {
            size_t rr = rowBase + ty * 4 + i;
            U[rr * 64 + o] = au[i][j] * sc;
            V[rr * 64 + o] = av[i][j] * sc + bi;
        }
    }
}

// ---------------------------------------------------------------------------
// gemm2gf: layer-2 GEMM (FFMA2 inner loop) with fused gather-A, max-over-k,
// AND fused xx of the output rows (exact FFMA2 lane arithmetic) -> xxo.
// ---------------------------------------------------------------------------
__global__ __launch_bounds__(256) void gemm2gf_kernel(
    const float* __restrict__ U, const float* __restrict__ Vv,
    const int* __restrict__ idx, const float* __restrict__ W,
    const float* __restrict__ sv, const float* __restrict__ bv,
    float* __restrict__ cat, int off, float* __restrict__ xxo)
{
    __shared__ __align__(16) float As[64][68];
    __shared__ __align__(16) float Ws[64][68];
    int tid = threadIdx.x;
    int i0 = blockIdx.x * 3;
    int r = tid >> 2, q0 = (tid & 3) * 4;
    {
        int i = i0 + r / 20;
        if (i >= BB * NN) i = BB * NN - 1;
        int p = i * 20 + (r % 20);
        int j = idx[p];
        int rbase = (i >> 12) << 12;
        const float4* urow = (const float4*)&U[(size_t)(rbase + j) * 64];
        const float4* vrow = (const float4*)&Vv[(size_t)i * 64];
#pragma unroll
        for (int q = q0; q < q0 + 4; q++) {
            float4 u = urow[q], v = vrow[q];
            As[q * 4 + 0][r] = lrelu(u.x + v.x);
            As[q * 4 + 1][r] = lrelu(u.y + v.y);
            As[q * 4 + 2][r] = lrelu(u.z + v.z);
            As[q * 4 + 3][r] = lrelu(u.w + v.w);
            float4 w4 = *(const float4*)&W[r * 64 + q * 4];
            Ws[q * 4 + 0][r] = w4.x; Ws[q * 4 + 1][r] = w4.y;
            Ws[q * 4 + 2][r] = w4.z; Ws[q * 4 + 3][r] = w4.w;
        }
    }
    __syncthreads();
    int ty = tid >> 4, tx = tid & 15;
    uint32_t wsB = (uint32_t)__cvta_generic_to_shared(&Ws[0][0]);
    unsigned long long accp[4][2] = {};
#pragma unroll 16
    for (int k = 0; k < 64; k++) {
        float4 a = *(const float4*)&As[k][ty * 4];
        unsigned long long wlo, whi;
        asm("ld.shared.v2.b64 {%0,%1}, [%2];"
            : "=l"(wlo), "=l"(whi) : "r"(wsB + (uint32_t)((k * 68 + tx * 4) * 4)));
        unsigned long long ax, ay, az, aw;
        asm("mov.b64 %0, {%1,%1};" : "=l"(ax) : "f"(a.x));
        asm("mov.b64 %0, {%1,%1};" : "=l"(ay) : "f"(a.y));
        asm("mov.b64 %0, {%1,%1};" : "=l"(az) : "f"(a.z));
        asm("mov.b64 %0, {%1,%1};" : "=l"(aw) : "f"(a.w));
        asm("fma.rn.f32x2 %0, %1, %2, %0;" : "+l"(accp[0][0]) : "l"(ax), "l"(wlo));
        asm("fma.rn.f32x2 %0, %1, %2, %0;" : "+l"(accp[0][1]) : "l"(ax), "l"(whi));
        asm("fma.rn.f32x2 %0, %1, %2, %0;" : "+l"(accp[1][0]) : "l"(ay), "l"(wlo));
        asm("fma.rn.f32x2 %0, %1, %2, %0;" : "+l"(accp[1][1]) : "l"(ay), "l"(whi));
        asm("fma.rn.f32x2 %0, %1, %2, %0;" : "+l"(accp[2][0]) : "l"(az), "l"(wlo));
        asm("fma.rn.f32x2 %0, %1, %2, %0;" : "+l"(accp[2][1]) : "l"(az), "l"(whi));
        asm("fma.rn.f32x2 %0, %1, %2, %0;" : "+l"(accp[3][0]) : "l"(aw), "l"(wlo));
        asm("fma.rn.f32x2 %0, %1, %2, %0;" : "+l"(accp[3][1]) : "l"(aw), "l"(whi));
    }
    float acc[4][4];
#pragma unroll
    for (int i = 0; i < 4; i++) {
        asm("mov.b64 {%0,%1}, %2;" : "=f"(acc[i][0]), "=f"(acc[i][1]) : "l"(accp[i][0]));
        asm("mov.b64 {%0,%1}, %2;" : "=f"(acc[i][2]), "=f"(acc[i][3]) : "l"(accp[i][1]));
    }

    float sc0 = sv[tx * 4 + 0], sc1 = sv[tx * 4 + 1], sc2 = sv[tx * 4 + 2], sc3 = sv[tx * 4 + 3];
    float bi0 = bv[tx * 4 + 0], bi1 = bv[tx * 4 + 1], bi2 = bv[tx * 4 + 2], bi3 = bv[tx * 4 + 3];
    __syncthreads();
#pragma unroll
    for (int i2 = 0; i2 < 4; i2++) {
        float4 vv;
        vv.x = lrelu(acc[i2][0] * sc0 + bi0);
        vv.y = lrelu(acc[i2][1] * sc1 + bi1);
        vv.z = lrelu(acc[i2][2] * sc2 + bi2);
        vv.w = lrelu(acc[i2][3] * sc3 + bi3);
        *(float4*)&As[ty * 4 + i2][tx * 4] = vv;
    }
    __syncthreads();
    if (tid < 192) {
        int pp = tid >> 6, o = tid & 63;
        int i = i0 + pp;
        if (i < BB * NN) {
            float m = As[pp * 20][o];
#pragma unroll
            for (int kk = 1; kk < KNBR; kk++)
                m = fmaxf(m, As[pp * 20 + kk][o]);
            cat[(size_t)i * 192 + off + o] = m;
            Ws[pp][o] = m;              // stage row for fused xx
        }
    }
    __syncthreads();
    if (tid < 3 && i0 + tid < BB * NN)
        xxo[i0 + tid] = xx_exact(&Ws[tid][0]);
}

// ---------------------------------------------------------------------------
// Stage-3 fused: out = max_k lrelu(U'[idx] + V'[i])
// ---------------------------------------------------------------------------
__global__ __launch_bounds__(256) void stage3_kernel(
    const float* __restrict__ U, const float* __restrict__ Vv,
    const int* __restrict__ idx, float* __restrict__ out)
{
    int tid = threadIdx.x, warp = tid >> 5, lane = tid & 31;
    int i = blockIdx.x * 8 + warp;
    int rbase = (i >> 12) << 12;
    float v0 = Vv[(size_t)i * 64 + lane];
    float v1 = Vv[(size_t)i * 64 + lane + 32];
    float m0 = -CUDART_INF_F, m1 = -CUDART_INF_F;
#pragma unroll
    for (int k = 0; k < KNBR; k++) {
        int j = idx[i * KNBR + k];
        const float* ur = &U[(size_t)(rbase + j) * 64];
        m0 = fmaxf(m0, lrelu(ur[lane] + v0));
        m1 = fmaxf(m1, lrelu(ur[lane + 32] + v1));
    }
    out[(size_t)i * 192 + 128 + lane] = m0;
    out[(size_t)i * 192 + 128 + lane + 32] = m1;
}

// ---------------------------------------------------------------------------
// Tiled fp32 GEMM (FFMA2 inner loop): 64x64x16 tiles, 4x4/thread.
// MODE 0 row-major float4 store; MODE 1 transposed final store;
// MODE 2 leaky+col-max (smem-reduced) -> single atomicMax per column.
// ---------------------------------------------------------------------------
template <int MODE, bool SB, bool EXT, bool LEAKY>
__global__ __launch_bounds__(256) void gemm_kernel(
    const float* __restrict__ A, int lda,
    const float* __restrict__ W, int ldw, int woff,
    const float* __restrict__ sv, const float* __restrict__ bv,
    const float* __restrict__ ext,
    float* __restrict__ outp, unsigned* __restrict__ gout,
    int Nout, int Ktot)
{
    __shared__ __align__(16) float As[16][68];
    __shared__ __align__(16) float Ws[16][68];
    __shared__ float cm[16][65];

    int tid = threadIdx.x;
    int tx = tid & 15, ty = tid >> 4;
    int rowBase = blockIdx.y * 64, colBase = blockIdx.x * 64;
    int lr = tid >> 2, lk = tid & 3;
    uint32_t wsB = (uint32_t)__cvta_generic_to_shared(&Ws[0][0]);

    unsigned long long accp[4][2] = {};

    for (int k0 = 0; k0 < Ktot; k0 += 16) {
        float4 av = *(const float4*)&A[(size_t)(rowBase + lr) * lda + k0 + lk * 4];
        float4 wv = make_float4(0.f, 0.f, 0.f, 0.f);
        if (colBase + lr < Nout)
            wv = *(const float4*)&W[(size_t)(colBase + lr) * ldw + woff + k0 + lk * 4];
        __syncthreads();
        As[lk * 4 + 0][lr] = av.x; As[lk * 4 + 1][lr] = av.y;
        As[lk * 4 + 2][lr] = av.z; As[lk * 4 + 3][lr] = av.w;
        Ws[lk * 4 + 0][lr] = wv.x; Ws[lk * 4 + 1][lr] = wv.y;
        Ws[lk * 4 + 2][lr] = wv.z; Ws[lk * 4 + 3][lr] = wv.w;
        __syncthreads();
#pragma unroll
        for (int k = 0; k < 16; k++) {
            float4 a = *(const float4*)&As[k][ty * 4];
            unsigned long long wlo, whi;
            asm("ld.shared.v2.b64 {%0,%1}, [%2];"
                : "=l"(wlo), "=l"(whi) : "r"(wsB + (uint32_t)((k * 68 + tx * 4) * 4)));
            unsigned long long ax, ay, az, aw;
            asm("mov.b64 %0, {%1,%1};" : "=l"(ax) : "f"(a.x));
            asm("mov.b64 %0, {%1,%1};" : "=l"(ay) : "f"(a.y));
            asm("mov.b64 %0, {%1,%1};" : "=l"(az) : "f"(a.z));
            asm("mov.b64 %0, {%1,%1};" : "=l"(aw) : "f"(a.w));
            asm("fma.rn.f32x2 %0, %1, %2, %0;" : "+l"(accp[0][0]) : "l"(ax), "l"(wlo));
            asm("fma.rn.f32x2 %0, %1, %2, %0;" : "+l"(accp[0][1]) : "l"(ax), "l"(whi));
            asm("fma.rn.f32x2 %0, %1, %2, %0;" : "+l"(accp[1][0]) : "l"(ay), "l"(wlo));
            asm("fma.rn.f32x2 %0, %1, %2, %0;" : "+l"(accp[1][1]) : "l"(ay), "l"(whi));
            asm("fma.rn.f32x2 %0, %1, %2, %0;" : "+l"(accp[2][0]) : "l"(az), "l"(wlo));
            asm("fma.rn.f32x2 %0, %1, %2, %0;" : "+l"(accp[2][1]) : "l"(az), "l"(whi));
            asm("fma.rn.f32x2 %0, %1, %2, %0;" : "+l"(accp[3][0]) : "l"(aw), "l"(wlo));
            asm("fma.rn.f32x2 %0, %1, %2, %0;" : "+l"(accp[3][1]) : "l"(aw), "l"(whi));
        }
    }

    float acc[4][4];
#pragma unroll
    for (int i = 0; i < 4; i++) {
        asm("mov.b64 {%0,%1}, %2;" : "=f"(acc[i][0]), "=f"(acc[i][1]) : "l"(accp[i][0]));
        asm("mov.b64 {%0,%1}, %2;" : "=f"(acc[i][2]), "=f"(acc[i][3]) : "l"(accp[i][1]));
    }

    int bidx = rowBase >> 12;

    if (MODE == 2) {
#pragma unroll
        for (int j = 0; j < 4; j++) {
            int o = colBase + tx * 4 + j;
            float sc = SB ? sv[o] : 1.f;
            float bi = SB ? bv[o] : 0.f;
            float m = -CUDART_INF_F;
#pragma unroll
            for (int i = 0; i < 4; i++) {
                float v = acc[i][j];
                if (SB) v = v * sc + bi;
                if (LEAKY) v = lrelu(v);
                m = fmaxf(m, v);
            }
            cm[ty][tx * 4 + j] = m;
        }
        __syncthreads();
        if (tid < 64) {
            float mm = cm[0][tid];
#pragma unroll
            for (int t = 1; t < 16; t++) mm = fmaxf(mm, cm[t][tid]);
            atomicMax(&gout[bidx * DIMG + colBase + tid], encf(mm));
        }
    } else if (MODE == 0) {
        float sc[4], bi[4], ex[4];
#pragma unroll
        for (int j = 0; j < 4; j++) {
            int o = colBase + tx * 4 + j;
            sc[j] = SB ? sv[o] : 1.f;
            bi[j] = SB ? bv[o] : 0.f;
            ex[j] = EXT ? ext[bidx * Nout + o] : 0.f;
        }
#pragma unroll
        for (int i = 0; i < 4; i++) {
            int r = rowBase + ty * 4 + i;
            float4 vv;
            float v0 = acc[i][0], v1 = acc[i][1], v2 = acc[i][2], v3 = acc[i][3];
            if (EXT) { v0 += ex[0]; v1 += ex[1]; v2 += ex[2]; v3 += ex[3]; }
            if (SB)  { v0 = v0 * sc[0] + bi[0]; v1 = v1 * sc[1] + bi[1];
                       v2 = v2 * sc[2] + bi[2]; v3 = v3 * sc[3] + bi[3]; }
            if (LEAKY) { v0 = lrelu(v0); v1 = lrelu(v1); v2 = lrelu(v2); v3 = lrelu(v3); }
            vv.x = v0; vv.y = v1; vv.z = v2; vv.w = v3;
            *(float4*)&outp[(size_t)r * Nout + colBase + tx * 4] = vv;
        }
    } else {
#pragma unroll
        for (int j = 0; j < 4; j++) {
            int o = colBase + tx * 4 + j;
#pragma unroll
            for (int i = 0; i < 4; i++) {
                int r = rowBase + ty * 4 + i;
                if (o < 13)
                    outp[((size_t)bidx * 13 + o) * NN + (r & (NN - 1))] = acc[i][j];
            }
        }
    }
}

// ---------------------------------------------------------------------------
// g-buffer init + gdot = w8[:, :1024] @ g  (per batch)
// ---------------------------------------------------------------------------
__global__ void zero_gu_kernel(unsigned* __restrict__ gu) {
    int t = blockIdx.x * blockDim.x + threadIdx.x;
    if (t < BB * DIMG) gu[t] = 0u;
}

__global__ __launch_bounds__(256) void gdot_kernel(
    const unsigned* __restrict__ gu, const float* __restrict__ w8, float* __restrict__ gdot)
{
    int b = blockIdx.x;
    __shared__ float gsh[DIMG];
    for (int i = threadIdx.x; i < DIMG; i += blockDim.x) gsh[i] = decf(gu[b * DIMG + i]);
    __syncthreads();
    int warp = threadIdx.x >> 5, lane = threadIdx.x & 31;
    for (int o = warp * 32; o < warp * 32 + 32; o++) {
        float accv = 0.f;
        for (int c = lane; c < DIMG; c += 32)
            accv += w8[(size_t)o * 1216 + c] * gsh[c];
#pragma unroll
        for (int off = 16; off; off >>= 1)
            accv += __shfl_down_sync(0xffffffffu, accv, off);
        if (lane == 0) gdot[b * 256 + o] = accv;
    }
}

// ---------------------------------------------------------------------------
// Launcher. knn64(stage2) sits at launch index 3 — the profiled slot.
// ---------------------------------------------------------------------------
extern "C" void kernel_launch(void* const* d_in, const int* in_sizes, int n_in,
                              void* d_out, int out_size)
{
    (void)in_sizes; (void)n_in; (void)out_size;

    const float* x   = (const float*)d_in[0];
    const float* w1  = (const float*)d_in[1];
    const float* s1  = (const float*)d_in[2];
    const float* b1  = (const float*)d_in[3];
    const float* w2  = (const float*)d_in[4];
    const float* s2  = (const float*)d_in[5];
    const float* b2  = (const float*)d_in[6];
    const float* w3  = (const float*)d_in[7];
    const float* s3  = (const float*)d_in[8];
    const float* b3  = (const float*)d_in[9];
    const float* w4  = (const float*)d_in[10];
    const float* s4  = (const float*)d_in[11];
    const float* b4  = (const float*)d_in[12];
    const float* w5  = (const float*)d_in[13];
    const float* s5  = (const float*)d_in[14];
    const float* b5  = (const float*)d_in[15];
    const float* w6  = (const float*)d_in[16];
    const float* s6  = (const float*)d_in[17];
    const float* b6  = (const float*)d_in[18];
    const float* w8  = (const float*)d_in[19];
    const float* s8  = (const float*)d_in[20];
    const float* b8  = (const float*)d_in[21];
    const float* w9  = (const float*)d_in[22];
    const float* s9  = (const float*)d_in[23];
    const float* b9  = (const float*)d_in[24];
    const float* w10 = (const float*)d_in[25];
    const float* s10 = (const float*)d_in[26];
    const float* b10 = (const float*)d_in[27];
    const float* w11 = (const float*)d_in[28];
    float* out = (float*)d_out;

    void* p;
    cudaGetSymbolAddress(&p, d_cat);   float*    cat   = (float*)p;
    cudaGetSymbolAddress(&p, d_idx);   int*      idx   = (int*)p;
    cudaGetSymbolAddress(&p, d_gu);    unsigned* gu    = (unsigned*)p;
    cudaGetSymbolAddress(&p, d_gdot);  float*    gdot  = (float*)p;
    cudaGetSymbolAddress(&p, d_h8);    float*    h8    = (float*)p;
    cudaGetSymbolAddress(&p, d_h9);    float*    h9    = (float*)p;
    cudaGetSymbolAddress(&p, d_h10);   float*    h10   = (float*)p;
    cudaGetSymbolAddress(&p, d_U);     float*    U     = (float*)p;
    cudaGetSymbolAddress(&p, d_V);     float*    V     = (float*)p;
    cudaGetSymbolAddress(&p, d_xx);    float*    xxb   = (float*)p;

    const int uvSmem = 3 * 64 * 68 * 4;   // 52224
    cudaFuncSetAttribute((const void*)uv64_kernel,
                         cudaFuncAttributeMaxDynamicSharedMemorySize, uvSmem);

    const int PTS = BB * NN;                 // 32768
    const int G2F = (PTS + 2) / 3;
    dim3 knnGrid(NN / 128, BB);

    // stage 1 (3 -> 64 -> 64); gemm2gf also emits xx(cat+0)
    knn3_kernel<<<knnGrid, 128>>>(x, idx);
    uv3_kernel<<<PTS / 8, 256>>>(x, w1, s1, b1, U, V);
    gemm2gf_kernel<<<G2F, 256>>>(U, V, idx, w2, s2, b2, cat, 0, xxb);

    // stage 2 (64 -> 64 -> 64) — knn64 at launch index 3 (profiled)
    knn64_kernel<<<knnGrid, 128>>>(cat + 0, 192, xxb, idx);
    uv64_kernel<<<PTS / 64, 256, uvSmem>>>(cat + 0, 192, w3, s3, b3, U, V);
    gemm2gf_kernel<<<G2F, 256>>>(U, V, idx, w4, s4, b4, cat, 64, xxb);

    // stage 3 (64 -> 64, single layer, fully fused)
    knn64_kernel<<<knnGrid, 128>>>(cat + 64, 192, xxb, idx);
    uv64_kernel<<<PTS / 64, 256, uvSmem>>>(cat + 64, 192, w5, s5, b5, U, V);
    stage3_kernel<<<PTS / 8, 256>>>(U, V, idx, cat);

    // cbl6 (192 -> 1024) fused with max-over-N (smem-reduced atomics)
    zero_gu_kernel<<<(BB * DIMG + 255) / 256, 256>>>(gu);
    gemm_kernel<2, true, false, true><<<dim3(DIMG / 64, PTS / 64), 256>>>(
        cat, 192, w6, 192, 0, s6, b6, nullptr, nullptr, gu, DIMG, 192);

    // gdot[b,o] = w8[o, :1024] . g[b]
    gdot_kernel<<<BB, 256>>>(gu, w8, gdot);

    // cbl8: (gdot + w8[:,1024:] @ cat) * s8 + b8, leaky
    gemm_kernel<0, true, true, true><<<dim3(256 / 64, PTS / 64), 256>>>(
        cat, 192, w8, 1216, 1024, s8, b8, gdot, h8, nullptr, 256, 192);

    // cbl9
    gemm_kernel<0, true, false, true><<<dim3(256 / 64, PTS / 64), 256>>>(
        h8, 256, w9, 256, 0, s9, b9, nullptr, h9, nullptr, 256, 256);

    // cbl10
    gemm_kernel<0, true, false, true><<<dim3(128 / 64, PTS / 64), 256>>>(
        h9, 256, w10, 256, 0, s10, b10, nullptr, h10, nullptr, 128, 256);

    // classifier + transpose to (B,13,N)
    gemm_kernel<1, false, false, false><<<dim3(1, PTS / 64), 256>>>(
        h10, 128, w11, 128, 0, nullptr, nullptr, nullptr, out, nullptr, 13, 128);
}